// round 13
// baseline (speedup 1.0000x reference)
#include <cuda_runtime.h>
#include <cuda_bf16.h>
#include <cstddef>

// Problem constants
#define BATCH 64
#define SEQ   128
#define HID   1024
#define EMB   512
#define ATT   512
#define VOC   32000
#define K2H   2048
#define M_ATT (SEQ*BATCH)   // 8192
#define NT_ATT 4
#define X0LD  2560          // EMB + 2H

// Output packing: logits | new_hidden | new_cell | alpha
#define OUT_LOGITS 0
#define OUT_HIDDEN 2048000
#define OUT_CELL   (2048000 + 131072)
#define OUT_ALPHA  (2048000 + 262144)

#define COMP  1.00035f      // B-truncation only (A exact via residual)
#define COMP2 1.00070f      // A and B truncation

// -------------------- scratch --------------------
struct Scratch {
    float dproj[BATCH * ATT];
    float dproj_part[8 * BATCH * ATT];
    float part[8 * M_ATT];
    float x0[BATCH * X0LD];
    float x0lo[BATCH * X0LD];
    float gates[8 * BATCH * 4 * HID];      // 8 k-slices
    float hlo[2 * BATCH * HID];
    float h0lo[BATCH * HID];
    float h1lo[BATCH * HID];
    __nv_bfloat16 enc_hi[M_ATT * K2H];
    __nv_bfloat16 enc_lo[M_ATT * K2H];
    __nv_bfloat16 wenc_hi[ATT * K2H];
    __nv_bfloat16 wenc_lo[ATT * K2H];
};
__device__ Scratch g_s;

// ===================== low-level helpers ==================================
__device__ __forceinline__ unsigned smem_u32(const void* p) {
    unsigned a;
    asm("{ .reg .u64 t; cvta.to.shared.u64 t, %1; cvt.u32.u64 %0, t; }"
        : "=r"(a) : "l"(p));
    return a;
}
__device__ __forceinline__ void ldm4(unsigned& r0, unsigned& r1,
                                     unsigned& r2, unsigned& r3, unsigned addr) {
    asm volatile("ldmatrix.sync.aligned.m8n8.x4.shared.b16 {%0,%1,%2,%3}, [%4];"
                 : "=r"(r0), "=r"(r1), "=r"(r2), "=r"(r3) : "r"(addr));
}
__device__ __forceinline__ void mma16816(float* d, const unsigned* a, const unsigned* b) {
    asm volatile(
        "mma.sync.aligned.m16n8k16.row.col.f32.bf16.bf16.f32 "
        "{%0,%1,%2,%3}, {%4,%5,%6,%7}, {%8,%9}, {%0,%1,%2,%3};"
        : "+f"(d[0]), "+f"(d[1]), "+f"(d[2]), "+f"(d[3])
        : "r"(a[0]), "r"(a[1]), "r"(a[2]), "r"(a[3]), "r"(b[0]), "r"(b[1]));
}
__device__ __forceinline__ void mma_tf32(float* d, const unsigned* a, const unsigned* b) {
    asm volatile(
        "mma.sync.aligned.m16n8k8.row.col.f32.tf32.tf32.f32 "
        "{%0,%1,%2,%3}, {%4,%5,%6,%7}, {%8,%9}, {%0,%1,%2,%3};"
        : "+f"(d[0]), "+f"(d[1]), "+f"(d[2]), "+f"(d[3])
        : "r"(a[0]), "r"(a[1]), "r"(a[2]), "r"(a[3]), "r"(b[0]), "r"(b[1]));
}
__device__ __forceinline__ void cpa16(unsigned dst, const void* src) {
    unsigned long long g = (unsigned long long)__cvta_generic_to_global(src);
    asm volatile("cp.async.cg.shared.global [%0], [%1], 16;"
                 :: "r"(dst), "l"(g) : "memory");
}
__device__ __forceinline__ void cpa_commit() {
    asm volatile("cp.async.commit_group;" ::: "memory");
}
template<int N> __device__ __forceinline__ void cpa_wait() {
    asm volatile("cp.async.wait_group %0;" :: "n"(N) : "memory");
}
__device__ __forceinline__ float tf32_lo(float x) {
    return x - __uint_as_float(__float_as_uint(x) & 0xffffe000u);
}
// 128-byte rows (f32 k32 tiles)
__device__ __forceinline__ unsigned swz128(int row, int colByte) {
    return row * 128 + (colByte ^ ((row & 7) << 4));
}
// 64-byte rows (bf16 k32 tiles)
__device__ __forceinline__ unsigned swz64(int row, int colByte) {
    return row * 64 + (colByte ^ (((row >> 1) & 3) << 4));
}

// bf16 fragment loads over 64B rows
__device__ __forceinline__ void load_afrag64(unsigned* f, unsigned base, int m0, int k0, int lane) {
    int j = lane >> 3, r = lane & 7;
    unsigned addr = base + swz64(m0 + (j & 1) * 8 + r, (k0 + (j >> 1) * 8) * 2);
    ldm4(f[0], f[1], f[2], f[3], addr);
}
__device__ __forceinline__ void load_bfrag64(unsigned* f01, unsigned* f23,
                                             unsigned base, int n0, int k0, int lane) {
    int j = lane >> 3, r = lane & 7;
    unsigned addr = base + swz64(n0 + (j >> 1) * 8 + r, (k0 + (j & 1) * 8) * 2);
    ldm4(f01[0], f01[1], f23[0], f23[1], addr);
}
// tf32 fragment loads over 128B rows
__device__ __forceinline__ void load_a32(unsigned* f, unsigned base, int m0, int k0, int lane) {
    int j = lane >> 3, r = lane & 7;
    unsigned addr = base + swz128(m0 + (j & 1) * 8 + r, k0 * 4 + (j >> 1) * 16);
    ldm4(f[0], f[1], f[2], f[3], addr);
}
__device__ __forceinline__ void load_b32(unsigned* g, unsigned base, int n0, int k0, int lane) {
    int j = lane >> 3, r = lane & 7;
    unsigned addr = base + swz128(n0 + (j >> 1) * 8 + r, k0 * 4 + (j & 1) * 16);
    ldm4(g[0], g[1], g[2], g[3], addr);
}

// ================= prepass: fp32 -> bf16 hi/lo planes =====================
__global__ void prep_bf16_kernel(const float* __restrict__ src,
                                 __nv_bfloat16* __restrict__ hi,
                                 __nv_bfloat16* __restrict__ lo, int n4)
{
    int i = blockIdx.x * blockDim.x + threadIdx.x;
    int stride = gridDim.x * blockDim.x;
    for (; i < n4; i += stride) {
        float4 v = ((const float4*)src)[i];
        __nv_bfloat162 h0 = __floats2bfloat162_rn(v.x, v.y);
        __nv_bfloat162 h1 = __floats2bfloat162_rn(v.z, v.w);
        float2 f0 = __bfloat1622float2(h0);
        float2 f1 = __bfloat1622float2(h1);
        __nv_bfloat162 l0 = __floats2bfloat162_rn(v.x - f0.x, v.y - f0.y);
        __nv_bfloat162 l1 = __floats2bfloat162_rn(v.z - f1.x, v.w - f1.y);
        ((uint2*)hi)[i] = make_uint2(*(unsigned*)&h0, *(unsigned*)&h1);
        ((uint2*)lo)[i] = make_uint2(*(unsigned*)&l0, *(unsigned*)&l1);
    }
}

// ================= prepass: tf32 residual plane ===========================
__global__ void prep_lo32_kernel(const float* __restrict__ src,
                                 float* __restrict__ lo, int n4)
{
    int i = blockIdx.x * blockDim.x + threadIdx.x;
    int stride = gridDim.x * blockDim.x;
    for (; i < n4; i += stride) {
        float4 v = ((const float4*)src)[i];
        float4 o;
        o.x = tf32_lo(v.x); o.y = tf32_lo(v.y);
        o.z = tf32_lo(v.z); o.w = tf32_lo(v.w);
        ((float4*)lo)[i] = o;
    }
}

// ======== attention energy: 3-stage pipelined bf16 3-term mma =============
// CTA tile 128M x 128N; K-chunk 32 bf16 (64B rows); stage 32KB x 3
#define ATT_STG 32768
__global__ __launch_bounds__(256, 2)
void attn_mma_kernel(const __nv_bfloat16* __restrict__ ehi,
                     const __nv_bfloat16* __restrict__ elo,
                     const __nv_bfloat16* __restrict__ whi,
                     const __nv_bfloat16* __restrict__ wlo,
                     const float* __restrict__ dproj, const float* __restrict__ v_w,
                     float* __restrict__ part)
{
    extern __shared__ __align__(128) unsigned char smn[];
    const int t = threadIdx.x, lane = t & 31, wid = t >> 5;
    const int warp_m = wid & 3;
    const int warp_n = wid >> 2;
    const int nBase = blockIdx.x * 128, mBase = blockIdx.y * 128;
    const unsigned sb = smem_u32(smn);

    float acc[2][8][4];
#pragma unroll
    for (int i = 0; i < 2; i++)
#pragma unroll
        for (int j = 0; j < 8; j++)
#pragma unroll
            for (int q = 0; q < 4; q++) acc[i][j][q] = 0.f;

    const int NCH = 64;
    auto prefetch = [&](int c) {
        const int stg = c % 3;
        const int k0 = c * 32;
        const unsigned aHi = sb + stg * ATT_STG;
        const unsigned aLo = aHi + 8192;
        const unsigned bHi = aHi + 16384;
        const unsigned bLo = aHi + 24576;
#pragma unroll
        for (int j = 0; j < 2; j++) {
            int u = j * 256 + t;
            int row = u >> 2, cc = u & 3;
            size_t off = (size_t)(mBase + row) * K2H + k0 + cc * 8;
            unsigned dst = swz64(row, cc * 16);
            cpa16(aHi + dst, ehi + off);
            cpa16(aLo + dst, elo + off);
        }
#pragma unroll
        for (int j = 0; j < 2; j++) {
            int u = j * 256 + t;
            int row = u >> 2, cc = u & 3;
            size_t off = (size_t)(nBase + row) * K2H + k0 + cc * 8;
            unsigned dst = swz64(row, cc * 16);
            cpa16(bHi + dst, whi + off);
            cpa16(bLo + dst, wlo + off);
        }
        cpa_commit();
    };

    prefetch(0); prefetch(1);
    for (int c = 0; c < NCH; c++) {
        if (c + 2 < NCH) { prefetch(c + 2); cpa_wait<2>(); }
        else if (c + 1 < NCH) cpa_wait<1>();
        else cpa_wait<0>();
        __syncthreads();
        const unsigned aHi = sb + (c % 3) * ATT_STG;
        const unsigned aLo = aHi + 8192;
        const unsigned bHi = aHi + 16384;
        const unsigned bLo = aHi + 24576;
#pragma unroll
        for (int ks = 0; ks < 2; ks++) {
            const int kk = ks * 16;
            unsigned ah[2][4], al[2][4];
#pragma unroll
            for (int mb = 0; mb < 2; mb++) {
                load_afrag64(ah[mb], aHi, warp_m * 32 + mb * 16, kk, lane);
                load_afrag64(al[mb], aLo, warp_m * 32 + mb * 16, kk, lane);
            }
#pragma unroll
            for (int p = 0; p < 4; p++) {
                unsigned bh[2][2], bl[2][2];
                load_bfrag64(bh[0], bh[1], bHi, warp_n * 64 + p * 16, kk, lane);
                load_bfrag64(bl[0], bl[1], bLo, warp_n * 64 + p * 16, kk, lane);
#pragma unroll
                for (int mb = 0; mb < 2; mb++)
#pragma unroll
                    for (int q = 0; q < 2; q++) {
                        int nb = p * 2 + q;
                        mma16816(acc[mb][nb], ah[mb], bh[q]);
                        mma16816(acc[mb][nb], ah[mb], bl[q]);
                        mma16816(acc[mb][nb], al[mb], bh[q]);
                    }
            }
        }
        __syncthreads();
    }

    // epilogue
    float* red = (float*)smn;
    const int quad = lane >> 2, qt = lane & 3;
#pragma unroll
    for (int mb = 0; mb < 2; mb++)
#pragma unroll
        for (int h = 0; h < 2; h++) {
            int row_local = warp_m * 32 + mb * 16 + quad + 8 * h;
            int g = mBase + row_local;
            int b = g & 63;
            float s = 0.f;
#pragma unroll
            for (int nb = 0; nb < 8; nb++) {
                int ng = nBase + warp_n * 64 + nb * 8 + qt * 2;
                float2 dp = *(const float2*)(dproj + (size_t)b * ATT + ng);
                float2 vv = *(const float2*)(v_w + ng);
                s += tanhf(acc[mb][nb][2 * h + 0] + dp.x) * vv.x
                   + tanhf(acc[mb][nb][2 * h + 1] + dp.y) * vv.y;
            }
            s += __shfl_xor_sync(0xffffffffu, s, 1);
            s += __shfl_xor_sync(0xffffffffu, s, 2);
            if (qt == 0) red[row_local * 2 + warp_n] = s;
        }
    __syncthreads();
    if (t < 128) {
        float s = red[t * 2] + red[t * 2 + 1];
        part[blockIdx.x * M_ATT + mBase + t] = s;
    }
}

// ========== pipelined tf32 GEMM (M=64), K-chunk 32, split-K ===============
template<int BN, int STAGES, bool ALO>
__global__ __launch_bounds__(256, (BN == 64) ? 3 : 2) void gemm_tf32_kernel(
    const float* __restrict__ A0, const float* __restrict__ A0lo, int lda0, int K0a,
    const float* __restrict__ A1, const float* __restrict__ A1lo, int lda1,
    const float* __restrict__ B0, int ldb0, int K0b,
    const float* __restrict__ B1, int ldb1,
    int sliceCh, float* __restrict__ C, int ldc, size_t cStride,
    const float* __restrict__ bias, float comp)
{
    extern __shared__ __align__(128) float smdyn[];
    constexpr int STGB = 8192 + (ALO ? 8192 : 0) + BN * 128;
    const int t = threadIdx.x, lane = t & 31, wid = t >> 5;
    const int warp_m = wid >> 2, warp_n = wid & 3;
    constexpr int NBW = BN / 32;
    const int nBase = blockIdx.x * BN;
    const int kOff = blockIdx.y * sliceCh * 32;
    C += (size_t)blockIdx.y * cStride;
    const unsigned sb = smem_u32(smdyn);

    float acc[2][NBW][4];
#pragma unroll
    for (int i = 0; i < 2; i++)
#pragma unroll
        for (int j = 0; j < NBW; j++)
#pragma unroll
            for (int q = 0; q < 4; q++) acc[i][j][q] = 0.f;

    auto prefetch = [&](int c) {
        const int k0 = kOff + c * 32;
        const unsigned aHi = sb + (c % STAGES) * STGB;
        const unsigned aLo = aHi + 8192;
        const unsigned bB  = aHi + 8192 + (ALO ? 8192 : 0);
#pragma unroll
        for (int j = 0; j < 2; j++) {
            int u = j * 256 + t;
            int row = u >> 3, cc = u & 7;
            int k = k0 + cc * 4;
            unsigned dst = swz128(row, cc * 16);
            if (k < K0a) {
                cpa16(aHi + dst, A0 + (size_t)row * lda0 + k);
                if (ALO) cpa16(aLo + dst, A0lo + (size_t)row * lda0 + k);
            } else {
                cpa16(aHi + dst, A1 + (size_t)row * lda1 + (k - K0a));
                if (ALO) cpa16(aLo + dst, A1lo + (size_t)row * lda1 + (k - K0a));
            }
        }
#pragma unroll
        for (int j = 0; j < BN / 32; j++) {
            int u = j * 256 + t;
            int row = u >> 3, cc = u & 7;
            int k = k0 + cc * 4;
            const float* src = (k < K0b)
                ? (B0 + (size_t)(nBase + row) * ldb0 + k)
                : (B1 + (size_t)(nBase + row) * ldb1 + (k - K0b));
            cpa16(bB + swz128(row, cc * 16), src);
        }
        cpa_commit();
    };

    const int nCh = sliceCh;
#pragma unroll
    for (int i = 0; i < STAGES - 1; i++)
        if (i < nCh) prefetch(i);
    for (int c = 0; c < nCh; c++) {
        if (c + STAGES - 1 < nCh) prefetch(c + STAGES - 1);
        int ahead = nCh - 1 - c;
        if (ahead > STAGES - 1) ahead = STAGES - 1;
        switch (ahead) {
            case 3: cpa_wait<3>(); break;
            case 2: cpa_wait<2>(); break;
            case 1: cpa_wait<1>(); break;
            default: cpa_wait<0>(); break;
        }
        __syncthreads();
        const unsigned aHi = sb + (c % STAGES) * STGB;
        const unsigned aLo = aHi + 8192;
        const unsigned bB  = aHi + 8192 + (ALO ? 8192 : 0);
#pragma unroll
        for (int ks = 0; ks < 4; ks++) {
            const int kk = ks * 8;
            unsigned ah[2][4], al[2][4], bg[NBW / 2][4];
#pragma unroll
            for (int mb = 0; mb < 2; mb++) {
                load_a32(ah[mb], aHi, warp_m * 32 + mb * 16, kk, lane);
                if (ALO) load_a32(al[mb], aLo, warp_m * 32 + mb * 16, kk, lane);
            }
#pragma unroll
            for (int p = 0; p < NBW / 2; p++)
                load_b32(bg[p], bB, warp_n * (8 * NBW) + p * 16, kk, lane);
#pragma unroll
            for (int mb = 0; mb < 2; mb++)
#pragma unroll
                for (int p = 0; p < NBW / 2; p++) {
                    mma_tf32(acc[mb][2 * p + 0], ah[mb], &bg[p][0]);
                    mma_tf32(acc[mb][2 * p + 1], ah[mb], &bg[p][2]);
                    if (ALO) {
                        mma_tf32(acc[mb][2 * p + 0], al[mb], &bg[p][0]);
                        mma_tf32(acc[mb][2 * p + 1], al[mb], &bg[p][2]);
                    }
                }
        }
        __syncthreads();
    }

    const int quad = lane >> 2, qt = lane & 3;
#pragma unroll
    for (int mb = 0; mb < 2; mb++)
#pragma unroll
        for (int nb = 0; nb < NBW; nb++) {
            int m = warp_m * 32 + mb * 16 + quad;
            int n = nBase + warp_n * (8 * NBW) + nb * 8 + qt * 2;
            float bx = 0.f, by = 0.f;
            if (bias) { float2 bb = *(const float2*)(bias + n); bx = bb.x; by = bb.y; }
            float2 o0, o1;
            o0.x = acc[mb][nb][0] * comp + bx; o0.y = acc[mb][nb][1] * comp + by;
            o1.x = acc[mb][nb][2] * comp + bx; o1.y = acc[mb][nb][3] * comp + by;
            *(float2*)(C + (size_t)m * ldc + n) = o0;
            *(float2*)(C + (size_t)(m + 8) * ldc + n) = o1;
        }
}

// ============ dproj partial reduce ========================================
__global__ void dproj_reduce_kernel(const float* __restrict__ part,
                                    float* __restrict__ out)
{
    int i = blockIdx.x * blockDim.x + threadIdx.x;
    float4 s = ((const float4*)part)[i];
#pragma unroll
    for (int sl = 1; sl < 8; sl++) {
        float4 v = ((const float4*)part)[sl * 8192 + i];
        s.x += v.x; s.y += v.y; s.z += v.z; s.w += v.w;
    }
    ((float4*)out)[i] = s;
}

// ============ fused softmax + context (alpha stays in smem) ===============
__global__ void softmax_context_kernel(const float* __restrict__ part,
                                       const float* __restrict__ enc,
                                       float* __restrict__ out_alpha,
                                       float* __restrict__ x0,
                                       float* __restrict__ x0lo)
{
    int b = blockIdx.x, t = threadIdx.x;          // 64 blocks x 256 threads
    __shared__ float sal[128];
    __shared__ float red[128];

    if (t < 128) {
        int r = t * 64 + b;
        float sc = 0.f;
#pragma unroll
        for (int nt = 0; nt < NT_ATT; nt++) sc += part[nt * M_ATT + r];
        sal[t] = sc;
        red[t] = sc;
    }
    __syncthreads();
    for (int off = 64; off; off >>= 1) {
        if (t < off) red[t] = fmaxf(red[t], red[t + off]);
        __syncthreads();
    }
    float mx = red[0];
    __syncthreads();
    if (t < 128) {
        float e = expf(sal[t] - mx);
        sal[t] = e;
        red[t] = e;
    }
    __syncthreads();
    for (int off = 64; off; off >>= 1) {
        if (t < off) red[t] += red[t + off];
        __syncthreads();
    }
    float inv = 1.f / red[0];
    __syncthreads();
    if (t < 128) {
        sal[t] *= inv;
        out_alpha[b * SEQ + t] = sal[t];
    }
    __syncthreads();

    // context: 2048 dims / 256 threads = 8 floats per thread
    int d0 = t * 8;
    float a0 = 0.f, a1 = 0.f, a2 = 0.f, a3 = 0.f;
    float a4 = 0.f, a5 = 0.f, a6 = 0.f, a7 = 0.f;
    for (int s = 0; s < SEQ; s++) {
        float al = sal[s];
        const float* e = enc + ((size_t)(s * 64 + b)) * K2H + d0;
        float4 v0 = *(const float4*)e;
        float4 v1 = *(const float4*)(e + 4);
        a0 += al * v0.x; a1 += al * v0.y; a2 += al * v0.z; a3 += al * v0.w;
        a4 += al * v1.x; a5 += al * v1.y; a6 += al * v1.z; a7 += al * v1.w;
    }
    float* xo = x0 + (size_t)b * X0LD + EMB + d0;
    float* xl = x0lo + (size_t)b * X0LD + EMB + d0;
    float4 w0; w0.x = a0; w0.y = a1; w0.z = a2; w0.w = a3;
    float4 w1; w1.x = a4; w1.y = a5; w1.z = a6; w1.w = a7;
    *(float4*)xo = w0; *(float4*)(xo + 4) = w1;
    float4 l0; l0.x = tf32_lo(a0); l0.y = tf32_lo(a1); l0.z = tf32_lo(a2); l0.w = tf32_lo(a3);
    float4 l1; l1.x = tf32_lo(a4); l1.y = tf32_lo(a5); l1.z = tf32_lo(a6); l1.w = tf32_lo(a7);
    *(float4*)xl = l0; *(float4*)(xl + 4) = l1;
}

// ================== embedding gather (+tf32 residual) =====================
__global__ void embed_kernel(const int* __restrict__ token,
                             const float* __restrict__ emb,
                             float* __restrict__ x0, float* __restrict__ x0lo)
{
    int b = blockIdx.x, t = threadIdx.x;
    float4 v = *(const float4*)(emb + (size_t)token[b] * EMB + t * 4);
    *(float4*)(x0 + (size_t)b * X0LD + t * 4) = v;
    float4 o;
    o.x = tf32_lo(v.x); o.y = tf32_lo(v.y); o.z = tf32_lo(v.z); o.w = tf32_lo(v.w);
    *(float4*)(x0lo + (size_t)b * X0LD + t * 4) = o;
}

// ========================== LSTM pointwise (sums 8 k-slices) ==============
__global__ void lstm_ew_kernel(const float* __restrict__ gates,
                               const float* __restrict__ b_ih,
                               const float* __restrict__ b_hh,
                               const float* __restrict__ c_in,
                               float* __restrict__ h_out,
                               float* __restrict__ c_out,
                               float* __restrict__ hlo_out)
{
    const size_t SL = (size_t)BATCH * 4 * HID;
    int b = blockIdx.x, t = threadIdx.x;
    const float* g0 = gates + (size_t)b * 4 * HID;
#pragma unroll
    for (int q = 0; q < 4; q++) {
        int j = t + q * 256;
        float gi = b_ih[j]            + b_hh[j];
        float gf = b_ih[HID + j]      + b_hh[HID + j];
        float gg = b_ih[2 * HID + j]  + b_hh[2 * HID + j];
        float go = b_ih[3 * HID + j]  + b_hh[3 * HID + j];
#pragma unroll
        for (int sl = 0; sl < 8; sl++) {
            const float* g = g0 + sl * SL;
            gi += g[j];
            gf += g[HID + j];
            gg += g[2 * HID + j];
            go += g[3 * HID + j];
        }
        float i_ = 1.f / (1.f + expf(-gi));
        float f_ = 1.f / (1.f + expf(-gf));
        float o_ = 1.f / (1.f + expf(-go));
        float cc = f_ * c_in[(size_t)b * HID + j] + i_ * tanhf(gg);
        float hh = o_ * tanhf(cc);
        c_out[(size_t)b * HID + j] = cc;
        h_out[(size_t)b * HID + j] = hh;
        hlo_out[(size_t)b * HID + j] = tf32_lo(hh);
    }
}

// ================================ driver ==================================
extern "C" void kernel_launch(void* const* d_in, const int* in_sizes, int n_in,
                              void* d_out, int out_size)
{
    const int*   token  = (const int*)  d_in[0];
    const float* hidden = (const float*)d_in[1];
    const float* cell   = (const float*)d_in[2];
    const float* enc    = (const float*)d_in[3];
    const float* emb    = (const float*)d_in[4];
    const float* W_enc  = (const float*)d_in[5];
    const float* W_dec  = (const float*)d_in[6];
    const float* v_w    = (const float*)d_in[7];
    const float* W_ih0  = (const float*)d_in[8];
    const float* W_hh0  = (const float*)d_in[9];
    const float* b_ih0  = (const float*)d_in[10];
    const float* b_hh0  = (const float*)d_in[11];
    const float* W_ih1  = (const float*)d_in[12];
    const float* W_hh1  = (const float*)d_in[13];
    const float* b_ih1  = (const float*)d_in[14];
    const float* b_hh1  = (const float*)d_in[15];
    const float* fc_W   = (const float*)d_in[16];
    const float* fc_b   = (const float*)d_in[17];

    float* out        = (float*)d_out;
    float* out_logits = out + OUT_LOGITS;
    float* out_hidden = out + OUT_HIDDEN;
    float* out_cell   = out + OUT_CELL;
    float* out_alpha  = out + OUT_ALPHA;

    Scratch* s = nullptr;
    cudaGetSymbolAddress((void**)&s, g_s);

    const int ATT_SMEM = 3 * ATT_STG;                       // 96 KB
    const int LS_SMEM  = 3 * (8192 + 8192 + 64 * 128);      // 72 KB
    const int FC_SMEM  = 4 * (8192 + 128 * 128);            // 96 KB
    cudaFuncSetAttribute(attn_mma_kernel,
                         cudaFuncAttributeMaxDynamicSharedMemorySize, ATT_SMEM);
    cudaFuncSetAttribute(gemm_tf32_kernel<64, 3, true>,
                         cudaFuncAttributeMaxDynamicSharedMemorySize, LS_SMEM);
    cudaFuncSetAttribute(gemm_tf32_kernel<128, 4, false>,
                         cudaFuncAttributeMaxDynamicSharedMemorySize, FC_SMEM);

    // 0) prepasses (single stream)
    prep_bf16_kernel<<<4096, 256>>>(enc, s->enc_hi, s->enc_lo, M_ATT * K2H / 4);
    prep_bf16_kernel<<<1024, 256>>>(W_enc, s->wenc_hi, s->wenc_lo, ATT * K2H / 4);
    prep_lo32_kernel<<<128, 256>>>(hidden, s->hlo, 2 * BATCH * HID / 4);

    // 1) dproj (split-K 8) + reduce
    gemm_tf32_kernel<64, 3, true><<<dim3(ATT / 64, 8), 256, LS_SMEM>>>(
        hidden + (size_t)BATCH * HID, s->hlo + (size_t)BATCH * HID, HID, HID,
        hidden, s->hlo, HID,
        W_dec, HID, HID, W_dec, HID,
        /*sliceCh=*/4, s->dproj_part, ATT, (size_t)BATCH * ATT, nullptr, COMP);
    dproj_reduce_kernel<<<32, 256>>>(s->dproj_part, s->dproj);

    // 2) attention energy (128x128 tiles) + fused tanh/v epilogue
    attn_mma_kernel<<<dim3(NT_ATT, M_ATT / 128), 256, ATT_SMEM>>>(
        s->enc_hi, s->enc_lo, s->wenc_hi, s->wenc_lo, s->dproj, v_w, s->part);

    // 3) fused softmax + context
    softmax_context_kernel<<<BATCH, 256>>>(s->part, enc, out_alpha, s->x0, s->x0lo);

    // 4) embed
    embed_kernel<<<BATCH, 128>>>(token, emb, s->x0, s->x0lo);

    // 5) LSTM layer 0 (split-K 8)
    gemm_tf32_kernel<64, 3, true><<<dim3(4 * HID / 64, 8), 256, LS_SMEM>>>(
        s->x0, s->x0lo, X0LD, X0LD,
        hidden, s->hlo, HID,
        W_ih0, X0LD, X0LD, W_hh0, HID,
        /*sliceCh=*/14, s->gates, 4 * HID, (size_t)BATCH * 4 * HID, nullptr, COMP);
    lstm_ew_kernel<<<BATCH, 256>>>(s->gates, b_ih0, b_hh0, cell,
                                   out_hidden, out_cell, s->h0lo);

    // 6) LSTM layer 1 (split-K 8)
    gemm_tf32_kernel<64, 3, true><<<dim3(4 * HID / 64, 8), 256, LS_SMEM>>>(
        out_hidden, s->h0lo, HID, HID,
        hidden + (size_t)BATCH * HID, s->hlo + (size_t)BATCH * HID, HID,
        W_ih1, HID, HID, W_hh1, HID,
        /*sliceCh=*/8, s->gates, 4 * HID, (size_t)BATCH * 4 * HID, nullptr, COMP);
    lstm_ew_kernel<<<BATCH, 256>>>(s->gates, b_ih1, b_hh1,
                                   cell + (size_t)BATCH * HID,
                                   out_hidden + (size_t)BATCH * HID,
                                   out_cell + (size_t)BATCH * HID, s->h1lo);

    // 7) fc logits (1-term tf32, COMP2, 4-stage)
    gemm_tf32_kernel<128, 4, false><<<dim3(VOC / 128, 1), 256, FC_SMEM>>>(
        out_hidden + (size_t)BATCH * HID, nullptr, HID, HID,
        s->x0 + EMB, nullptr, X0LD,
        fc_W, 3 * HID, 3 * HID, fc_W, 3 * HID,
        /*sliceCh=*/96, out_logits, VOC, 0, fc_b, COMP2);
}

// round 14
// speedup vs baseline: 1.0446x; 1.0446x over previous
#include <cuda_runtime.h>
#include <cuda_bf16.h>
#include <cstddef>

// Problem constants
#define BATCH 64
#define SEQ   128
#define HID   1024
#define EMB   512
#define ATT   512
#define VOC   32000
#define K2H   2048
#define M_ATT (SEQ*BATCH)   // 8192
#define NT_ATT 4
#define X0LD  2560          // EMB + 2H

// Output packing: logits | new_hidden | new_cell | alpha
#define OUT_LOGITS 0
#define OUT_HIDDEN 2048000
#define OUT_CELL   (2048000 + 131072)
#define OUT_ALPHA  (2048000 + 262144)

#define COMP  1.00035f      // B-truncation only (A exact via residual)
#define COMP2 1.00070f      // A and B truncation

// -------------------- scratch --------------------
struct Scratch {
    float dproj[BATCH * ATT];
    float dproj_part[8 * BATCH * ATT];
    float part[8 * M_ATT];
    float x0[BATCH * X0LD];
    float x0lo[BATCH * X0LD];
    float gates[8 * BATCH * 4 * HID];      // 8 k-slices
    float hlo[2 * BATCH * HID];
    float h0lo[BATCH * HID];
    float h1lo[BATCH * HID];
    __nv_bfloat16 enc_hi[M_ATT * K2H];
    __nv_bfloat16 enc_lo[M_ATT * K2H];
    __nv_bfloat16 wenc_hi[ATT * K2H];
    __nv_bfloat16 wenc_lo[ATT * K2H];
};
__device__ Scratch g_s;

// ===================== low-level helpers ==================================
__device__ __forceinline__ unsigned smem_u32(const void* p) {
    unsigned a;
    asm("{ .reg .u64 t; cvta.to.shared.u64 t, %1; cvt.u32.u64 %0, t; }"
        : "=r"(a) : "l"(p));
    return a;
}
__device__ __forceinline__ void ldm4(unsigned& r0, unsigned& r1,
                                     unsigned& r2, unsigned& r3, unsigned addr) {
    asm volatile("ldmatrix.sync.aligned.m8n8.x4.shared.b16 {%0,%1,%2,%3}, [%4];"
                 : "=r"(r0), "=r"(r1), "=r"(r2), "=r"(r3) : "r"(addr));
}
__device__ __forceinline__ void mma16816(float* d, const unsigned* a, const unsigned* b) {
    asm volatile(
        "mma.sync.aligned.m16n8k16.row.col.f32.bf16.bf16.f32 "
        "{%0,%1,%2,%3}, {%4,%5,%6,%7}, {%8,%9}, {%0,%1,%2,%3};"
        : "+f"(d[0]), "+f"(d[1]), "+f"(d[2]), "+f"(d[3])
        : "r"(a[0]), "r"(a[1]), "r"(a[2]), "r"(a[3]), "r"(b[0]), "r"(b[1]));
}
__device__ __forceinline__ void mma_tf32(float* d, const unsigned* a, const unsigned* b) {
    asm volatile(
        "mma.sync.aligned.m16n8k8.row.col.f32.tf32.tf32.f32 "
        "{%0,%1,%2,%3}, {%4,%5,%6,%7}, {%8,%9}, {%0,%1,%2,%3};"
        : "+f"(d[0]), "+f"(d[1]), "+f"(d[2]), "+f"(d[3])
        : "r"(a[0]), "r"(a[1]), "r"(a[2]), "r"(a[3]), "r"(b[0]), "r"(b[1]));
}
__device__ __forceinline__ void cpa16(unsigned dst, const void* src) {
    unsigned long long g = (unsigned long long)__cvta_generic_to_global(src);
    asm volatile("cp.async.cg.shared.global [%0], [%1], 16;"
                 :: "r"(dst), "l"(g) : "memory");
}
__device__ __forceinline__ void cpa_commit() {
    asm volatile("cp.async.commit_group;" ::: "memory");
}
template<int N> __device__ __forceinline__ void cpa_wait() {
    asm volatile("cp.async.wait_group %0;" :: "n"(N) : "memory");
}
__device__ __forceinline__ float tf32_lo(float x) {
    return x - __uint_as_float(__float_as_uint(x) & 0xffffe000u);
}
// 128-byte rows (f32 k32 tiles)
__device__ __forceinline__ unsigned swz128(int row, int colByte) {
    return row * 128 + (colByte ^ ((row & 7) << 4));
}
// 64-byte rows (bf16 k32 tiles)
__device__ __forceinline__ unsigned swz64(int row, int colByte) {
    return row * 64 + (colByte ^ (((row >> 1) & 3) << 4));
}

// bf16 fragment loads over 64B rows
__device__ __forceinline__ void load_afrag64(unsigned* f, unsigned base, int m0, int k0, int lane) {
    int j = lane >> 3, r = lane & 7;
    unsigned addr = base + swz64(m0 + (j & 1) * 8 + r, (k0 + (j >> 1) * 8) * 2);
    ldm4(f[0], f[1], f[2], f[3], addr);
}
__device__ __forceinline__ void load_bfrag64(unsigned* f01, unsigned* f23,
                                             unsigned base, int n0, int k0, int lane) {
    int j = lane >> 3, r = lane & 7;
    unsigned addr = base + swz64(n0 + (j >> 1) * 8 + r, (k0 + (j & 1) * 8) * 2);
    ldm4(f01[0], f01[1], f23[0], f23[1], addr);
}
// tf32 fragment loads over 128B rows
__device__ __forceinline__ void load_a32(unsigned* f, unsigned base, int m0, int k0, int lane) {
    int j = lane >> 3, r = lane & 7;
    unsigned addr = base + swz128(m0 + (j & 1) * 8 + r, k0 * 4 + (j >> 1) * 16);
    ldm4(f[0], f[1], f[2], f[3], addr);
}
__device__ __forceinline__ void load_b32(unsigned* g, unsigned base, int n0, int k0, int lane) {
    int j = lane >> 3, r = lane & 7;
    unsigned addr = base + swz128(n0 + (j >> 1) * 8 + r, k0 * 4 + (j & 1) * 16);
    ldm4(g[0], g[1], g[2], g[3], addr);
}

// ================= prepass: fp32 -> bf16 hi/lo planes =====================
__global__ void prep_bf16_kernel(const float* __restrict__ src,
                                 __nv_bfloat16* __restrict__ hi,
                                 __nv_bfloat16* __restrict__ lo, int n4)
{
    int i = blockIdx.x * blockDim.x + threadIdx.x;
    int stride = gridDim.x * blockDim.x;
    for (; i < n4; i += stride) {
        float4 v = ((const float4*)src)[i];
        __nv_bfloat162 h0 = __floats2bfloat162_rn(v.x, v.y);
        __nv_bfloat162 h1 = __floats2bfloat162_rn(v.z, v.w);
        float2 f0 = __bfloat1622float2(h0);
        float2 f1 = __bfloat1622float2(h1);
        __nv_bfloat162 l0 = __floats2bfloat162_rn(v.x - f0.x, v.y - f0.y);
        __nv_bfloat162 l1 = __floats2bfloat162_rn(v.z - f1.x, v.w - f1.y);
        ((uint2*)hi)[i] = make_uint2(*(unsigned*)&h0, *(unsigned*)&h1);
        ((uint2*)lo)[i] = make_uint2(*(unsigned*)&l0, *(unsigned*)&l1);
    }
}

// ================= prepass: tf32 residual plane ===========================
__global__ void prep_lo32_kernel(const float* __restrict__ src,
                                 float* __restrict__ lo, int n4)
{
    int i = blockIdx.x * blockDim.x + threadIdx.x;
    int stride = gridDim.x * blockDim.x;
    for (; i < n4; i += stride) {
        float4 v = ((const float4*)src)[i];
        float4 o;
        o.x = tf32_lo(v.x); o.y = tf32_lo(v.y);
        o.z = tf32_lo(v.z); o.w = tf32_lo(v.w);
        ((float4*)lo)[i] = o;
    }
}

// ======== attention energy: 3-stage pipelined bf16 3-term mma =============
// CTA tile 128M x 128N; K-chunk 32 bf16 (64B rows); stage 32KB x 3
#define ATT_STG 32768
__global__ __launch_bounds__(256, 2)
void attn_mma_kernel(const __nv_bfloat16* __restrict__ ehi,
                     const __nv_bfloat16* __restrict__ elo,
                     const __nv_bfloat16* __restrict__ whi,
                     const __nv_bfloat16* __restrict__ wlo,
                     const float* __restrict__ dproj, const float* __restrict__ v_w,
                     float* __restrict__ part)
{
    extern __shared__ __align__(128) unsigned char smn[];
    const int t = threadIdx.x, lane = t & 31, wid = t >> 5;
    const int warp_m = wid & 3;
    const int warp_n = wid >> 2;
    const int nBase = blockIdx.x * 128, mBase = blockIdx.y * 128;
    const unsigned sb = smem_u32(smn);

    float acc[2][8][4];
#pragma unroll
    for (int i = 0; i < 2; i++)
#pragma unroll
        for (int j = 0; j < 8; j++)
#pragma unroll
            for (int q = 0; q < 4; q++) acc[i][j][q] = 0.f;

    const int NCH = 64;
    auto prefetch = [&](int c) {
        const int stg = c % 3;
        const int k0 = c * 32;
        const unsigned aHi = sb + stg * ATT_STG;
        const unsigned aLo = aHi + 8192;
        const unsigned bHi = aHi + 16384;
        const unsigned bLo = aHi + 24576;
#pragma unroll
        for (int j = 0; j < 2; j++) {
            int u = j * 256 + t;
            int row = u >> 2, cc = u & 3;
            size_t off = (size_t)(mBase + row) * K2H + k0 + cc * 8;
            unsigned dst = swz64(row, cc * 16);
            cpa16(aHi + dst, ehi + off);
            cpa16(aLo + dst, elo + off);
        }
#pragma unroll
        for (int j = 0; j < 2; j++) {
            int u = j * 256 + t;
            int row = u >> 2, cc = u & 3;
            size_t off = (size_t)(nBase + row) * K2H + k0 + cc * 8;
            unsigned dst = swz64(row, cc * 16);
            cpa16(bHi + dst, whi + off);
            cpa16(bLo + dst, wlo + off);
        }
        cpa_commit();
    };

    prefetch(0); prefetch(1);
    for (int c = 0; c < NCH; c++) {
        if (c + 2 < NCH) { prefetch(c + 2); cpa_wait<2>(); }
        else if (c + 1 < NCH) cpa_wait<1>();
        else cpa_wait<0>();
        __syncthreads();
        const unsigned aHi = sb + (c % 3) * ATT_STG;
        const unsigned aLo = aHi + 8192;
        const unsigned bHi = aHi + 16384;
        const unsigned bLo = aHi + 24576;
#pragma unroll
        for (int ks = 0; ks < 2; ks++) {
            const int kk = ks * 16;
            unsigned ah[2][4], al[2][4];
#pragma unroll
            for (int mb = 0; mb < 2; mb++) {
                load_afrag64(ah[mb], aHi, warp_m * 32 + mb * 16, kk, lane);
                load_afrag64(al[mb], aLo, warp_m * 32 + mb * 16, kk, lane);
            }
#pragma unroll
            for (int p = 0; p < 4; p++) {
                unsigned bh[2][2], bl[2][2];
                load_bfrag64(bh[0], bh[1], bHi, warp_n * 64 + p * 16, kk, lane);
                load_bfrag64(bl[0], bl[1], bLo, warp_n * 64 + p * 16, kk, lane);
#pragma unroll
                for (int mb = 0; mb < 2; mb++)
#pragma unroll
                    for (int q = 0; q < 2; q++) {
                        int nb = p * 2 + q;
                        mma16816(acc[mb][nb], ah[mb], bh[q]);
                        mma16816(acc[mb][nb], ah[mb], bl[q]);
                        mma16816(acc[mb][nb], al[mb], bh[q]);
                    }
            }
        }
        __syncthreads();
    }

    // epilogue
    float* red = (float*)smn;
    const int quad = lane >> 2, qt = lane & 3;
#pragma unroll
    for (int mb = 0; mb < 2; mb++)
#pragma unroll
        for (int h = 0; h < 2; h++) {
            int row_local = warp_m * 32 + mb * 16 + quad + 8 * h;
            int g = mBase + row_local;
            int b = g & 63;
            float s = 0.f;
#pragma unroll
            for (int nb = 0; nb < 8; nb++) {
                int ng = nBase + warp_n * 64 + nb * 8 + qt * 2;
                float2 dp = *(const float2*)(dproj + (size_t)b * ATT + ng);
                float2 vv = *(const float2*)(v_w + ng);
                s += tanhf(acc[mb][nb][2 * h + 0] + dp.x) * vv.x
                   + tanhf(acc[mb][nb][2 * h + 1] + dp.y) * vv.y;
            }
            s += __shfl_xor_sync(0xffffffffu, s, 1);
            s += __shfl_xor_sync(0xffffffffu, s, 2);
            if (qt == 0) red[row_local * 2 + warp_n] = s;
        }
    __syncthreads();
    if (t < 128) {
        float s = red[t * 2] + red[t * 2 + 1];
        part[blockIdx.x * M_ATT + mBase + t] = s;
    }
}

// ========== pipelined tf32 GEMM (M=64), K-chunk 32, split-K ===============
template<int BN, int STAGES, bool ALO>
__global__ __launch_bounds__(256, (BN == 64) ? 3 : 2) void gemm_tf32_kernel(
    const float* __restrict__ A0, const float* __restrict__ A0lo, int lda0, int K0a,
    const float* __restrict__ A1, const float* __restrict__ A1lo, int lda1,
    const float* __restrict__ B0, int ldb0, int K0b,
    const float* __restrict__ B1, int ldb1,
    int sliceCh, float* __restrict__ C, int ldc, size_t cStride,
    const float* __restrict__ bias, float comp)
{
    extern __shared__ __align__(128) float smdyn[];
    constexpr int STGB = 8192 + (ALO ? 8192 : 0) + BN * 128;
    const int t = threadIdx.x, lane = t & 31, wid = t >> 5;
    const int warp_m = wid >> 2, warp_n = wid & 3;
    constexpr int NBW = BN / 32;
    const int nBase = blockIdx.x * BN;
    const int kOff = blockIdx.y * sliceCh * 32;
    C += (size_t)blockIdx.y * cStride;
    const unsigned sb = smem_u32(smdyn);

    float acc[2][NBW][4];
#pragma unroll
    for (int i = 0; i < 2; i++)
#pragma unroll
        for (int j = 0; j < NBW; j++)
#pragma unroll
            for (int q = 0; q < 4; q++) acc[i][j][q] = 0.f;

    auto prefetch = [&](int c) {
        const int k0 = kOff + c * 32;
        const unsigned aHi = sb + (c % STAGES) * STGB;
        const unsigned aLo = aHi + 8192;
        const unsigned bB  = aHi + 8192 + (ALO ? 8192 : 0);
#pragma unroll
        for (int j = 0; j < 2; j++) {
            int u = j * 256 + t;
            int row = u >> 3, cc = u & 7;
            int k = k0 + cc * 4;
            unsigned dst = swz128(row, cc * 16);
            if (k < K0a) {
                cpa16(aHi + dst, A0 + (size_t)row * lda0 + k);
                if (ALO) cpa16(aLo + dst, A0lo + (size_t)row * lda0 + k);
            } else {
                cpa16(aHi + dst, A1 + (size_t)row * lda1 + (k - K0a));
                if (ALO) cpa16(aLo + dst, A1lo + (size_t)row * lda1 + (k - K0a));
            }
        }
#pragma unroll
        for (int j = 0; j < BN / 32; j++) {
            int u = j * 256 + t;
            int row = u >> 3, cc = u & 7;
            int k = k0 + cc * 4;
            const float* src = (k < K0b)
                ? (B0 + (size_t)(nBase + row) * ldb0 + k)
                : (B1 + (size_t)(nBase + row) * ldb1 + (k - K0b));
            cpa16(bB + swz128(row, cc * 16), src);
        }
        cpa_commit();
    };

    const int nCh = sliceCh;
#pragma unroll
    for (int i = 0; i < STAGES - 1; i++)
        if (i < nCh) prefetch(i);
    for (int c = 0; c < nCh; c++) {
        if (c + STAGES - 1 < nCh) prefetch(c + STAGES - 1);
        int ahead = nCh - 1 - c;
        if (ahead > STAGES - 1) ahead = STAGES - 1;
        switch (ahead) {
            case 3: cpa_wait<3>(); break;
            case 2: cpa_wait<2>(); break;
            case 1: cpa_wait<1>(); break;
            default: cpa_wait<0>(); break;
        }
        __syncthreads();
        const unsigned aHi = sb + (c % STAGES) * STGB;
        const unsigned aLo = aHi + 8192;
        const unsigned bB  = aHi + 8192 + (ALO ? 8192 : 0);
#pragma unroll
        for (int ks = 0; ks < 4; ks++) {
            const int kk = ks * 8;
            unsigned ah[2][4], al[2][4], bg[NBW / 2][4];
#pragma unroll
            for (int mb = 0; mb < 2; mb++) {
                load_a32(ah[mb], aHi, warp_m * 32 + mb * 16, kk, lane);
                if (ALO) load_a32(al[mb], aLo, warp_m * 32 + mb * 16, kk, lane);
            }
#pragma unroll
            for (int p = 0; p < NBW / 2; p++)
                load_b32(bg[p], bB, warp_n * (8 * NBW) + p * 16, kk, lane);
#pragma unroll
            for (int mb = 0; mb < 2; mb++)
#pragma unroll
                for (int p = 0; p < NBW / 2; p++) {
                    mma_tf32(acc[mb][2 * p + 0], ah[mb], &bg[p][0]);
                    mma_tf32(acc[mb][2 * p + 1], ah[mb], &bg[p][2]);
                    if (ALO) {
                        mma_tf32(acc[mb][2 * p + 0], al[mb], &bg[p][0]);
                        mma_tf32(acc[mb][2 * p + 1], al[mb], &bg[p][2]);
                    }
                }
        }
        __syncthreads();
    }

    const int quad = lane >> 2, qt = lane & 3;
#pragma unroll
    for (int mb = 0; mb < 2; mb++)
#pragma unroll
        for (int nb = 0; nb < NBW; nb++) {
            int m = warp_m * 32 + mb * 16 + quad;
            int n = nBase + warp_n * (8 * NBW) + nb * 8 + qt * 2;
            float bx = 0.f, by = 0.f;
            if (bias) { float2 bb = *(const float2*)(bias + n); bx = bb.x; by = bb.y; }
            float2 o0, o1;
            o0.x = acc[mb][nb][0] * comp + bx; o0.y = acc[mb][nb][1] * comp + by;
            o1.x = acc[mb][nb][2] * comp + bx; o1.y = acc[mb][nb][3] * comp + by;
            *(float2*)(C + (size_t)m * ldc + n) = o0;
            *(float2*)(C + (size_t)(m + 8) * ldc + n) = o1;
        }
}

// ============ dproj partial reduce ========================================
__global__ void dproj_reduce_kernel(const float* __restrict__ part,
                                    float* __restrict__ out)
{
    int i = blockIdx.x * blockDim.x + threadIdx.x;
    float4 s = ((const float4*)part)[i];
#pragma unroll
    for (int sl = 1; sl < 8; sl++) {
        float4 v = ((const float4*)part)[sl * 8192 + i];
        s.x += v.x; s.y += v.y; s.z += v.z; s.w += v.w;
    }
    ((float4*)out)[i] = s;
}

// ===== fused softmax + context, full parallelism: grid (4, BATCH) =========
// Each x-block redundantly computes the 128-wide softmax in smem, then
// handles its 512-dim slice of context (256 thr x 2 floats — same access
// pattern as the old standalone context kernel). x-block 0 writes alpha.
__global__ void softmax_context_kernel(const float* __restrict__ part,
                                       const float* __restrict__ enc,
                                       float* __restrict__ out_alpha,
                                       float* __restrict__ x0,
                                       float* __restrict__ x0lo)
{
    int b = blockIdx.y, t = threadIdx.x;
    __shared__ float sal[128];
    __shared__ float red[128];

    if (t < 128) {
        int r = t * 64 + b;
        float sc = 0.f;
#pragma unroll
        for (int nt = 0; nt < NT_ATT; nt++) sc += part[nt * M_ATT + r];
        sal[t] = sc;
        red[t] = sc;
    }
    __syncthreads();
    for (int off = 64; off; off >>= 1) {
        if (t < off) red[t] = fmaxf(red[t], red[t + off]);
        __syncthreads();
    }
    float mx = red[0];
    __syncthreads();
    if (t < 128) {
        float e = expf(sal[t] - mx);
        sal[t] = e;
        red[t] = e;
    }
    __syncthreads();
    for (int off = 64; off; off >>= 1) {
        if (t < off) red[t] += red[t + off];
        __syncthreads();
    }
    float inv = 1.f / red[0];
    __syncthreads();
    if (t < 128) {
        sal[t] *= inv;
        if (blockIdx.x == 0) out_alpha[b * SEQ + t] = sal[t];
    }
    __syncthreads();

    // context slice: dims [blockIdx.x*512, +512), 2 floats per thread
    int d0 = blockIdx.x * 512 + t * 2;
    float ax = 0.f, ay = 0.f;
#pragma unroll 4
    for (int s = 0; s < SEQ; s++) {
        float2 e = *(const float2*)(enc + ((size_t)(s * 64 + b)) * K2H + d0);
        ax += sal[s] * e.x;
        ay += sal[s] * e.y;
    }
    float2 o; o.x = ax; o.y = ay;
    *(float2*)(x0 + (size_t)b * X0LD + EMB + d0) = o;
    float2 l; l.x = tf32_lo(ax); l.y = tf32_lo(ay);
    *(float2*)(x0lo + (size_t)b * X0LD + EMB + d0) = l;
}

// ================== embedding gather (+tf32 residual) =====================
__global__ void embed_kernel(const int* __restrict__ token,
                             const float* __restrict__ emb,
                             float* __restrict__ x0, float* __restrict__ x0lo)
{
    int b = blockIdx.x, t = threadIdx.x;
    float4 v = *(const float4*)(emb + (size_t)token[b] * EMB + t * 4);
    *(float4*)(x0 + (size_t)b * X0LD + t * 4) = v;
    float4 o;
    o.x = tf32_lo(v.x); o.y = tf32_lo(v.y); o.z = tf32_lo(v.z); o.w = tf32_lo(v.w);
    *(float4*)(x0lo + (size_t)b * X0LD + t * 4) = o;
}

// ========================== LSTM pointwise (sums 8 k-slices) ==============
__global__ void lstm_ew_kernel(const float* __restrict__ gates,
                               const float* __restrict__ b_ih,
                               const float* __restrict__ b_hh,
                               const float* __restrict__ c_in,
                               float* __restrict__ h_out,
                               float* __restrict__ c_out,
                               float* __restrict__ hlo_out)
{
    const size_t SL = (size_t)BATCH * 4 * HID;
    int b = blockIdx.x, t = threadIdx.x;
    const float* g0 = gates + (size_t)b * 4 * HID;
#pragma unroll
    for (int q = 0; q < 4; q++) {
        int j = t + q * 256;
        float gi = b_ih[j]            + b_hh[j];
        float gf = b_ih[HID + j]      + b_hh[HID + j];
        float gg = b_ih[2 * HID + j]  + b_hh[2 * HID + j];
        float go = b_ih[3 * HID + j]  + b_hh[3 * HID + j];
#pragma unroll
        for (int sl = 0; sl < 8; sl++) {
            const float* g = g0 + sl * SL;
            gi += g[j];
            gf += g[HID + j];
            gg += g[2 * HID + j];
            go += g[3 * HID + j];
        }
        float i_ = 1.f / (1.f + expf(-gi));
        float f_ = 1.f / (1.f + expf(-gf));
        float o_ = 1.f / (1.f + expf(-go));
        float cc = f_ * c_in[(size_t)b * HID + j] + i_ * tanhf(gg);
        float hh = o_ * tanhf(cc);
        c_out[(size_t)b * HID + j] = cc;
        h_out[(size_t)b * HID + j] = hh;
        hlo_out[(size_t)b * HID + j] = tf32_lo(hh);
    }
}

// ================================ driver ==================================
extern "C" void kernel_launch(void* const* d_in, const int* in_sizes, int n_in,
                              void* d_out, int out_size)
{
    const int*   token  = (const int*)  d_in[0];
    const float* hidden = (const float*)d_in[1];
    const float* cell   = (const float*)d_in[2];
    const float* enc    = (const float*)d_in[3];
    const float* emb    = (const float*)d_in[4];
    const float* W_enc  = (const float*)d_in[5];
    const float* W_dec  = (const float*)d_in[6];
    const float* v_w    = (const float*)d_in[7];
    const float* W_ih0  = (const float*)d_in[8];
    const float* W_hh0  = (const float*)d_in[9];
    const float* b_ih0  = (const float*)d_in[10];
    const float* b_hh0  = (const float*)d_in[11];
    const float* W_ih1  = (const float*)d_in[12];
    const float* W_hh1  = (const float*)d_in[13];
    const float* b_ih1  = (const float*)d_in[14];
    const float* b_hh1  = (const float*)d_in[15];
    const float* fc_W   = (const float*)d_in[16];
    const float* fc_b   = (const float*)d_in[17];

    float* out        = (float*)d_out;
    float* out_logits = out + OUT_LOGITS;
    float* out_hidden = out + OUT_HIDDEN;
    float* out_cell   = out + OUT_CELL;
    float* out_alpha  = out + OUT_ALPHA;

    Scratch* s = nullptr;
    cudaGetSymbolAddress((void**)&s, g_s);

    const int ATT_SMEM = 3 * ATT_STG;                       // 96 KB
    const int LS_SMEM  = 3 * (8192 + 8192 + 64 * 128);      // 72 KB
    const int FC_SMEM  = 4 * (8192 + 128 * 128);            // 96 KB
    cudaFuncSetAttribute(attn_mma_kernel,
                         cudaFuncAttributeMaxDynamicSharedMemorySize, ATT_SMEM);
    cudaFuncSetAttribute(gemm_tf32_kernel<64, 3, true>,
                         cudaFuncAttributeMaxDynamicSharedMemorySize, LS_SMEM);
    cudaFuncSetAttribute(gemm_tf32_kernel<128, 4, false>,
                         cudaFuncAttributeMaxDynamicSharedMemorySize, FC_SMEM);

    // 0) prepasses (single stream, round-11 order)
    prep_bf16_kernel<<<4096, 256>>>(enc, s->enc_hi, s->enc_lo, M_ATT * K2H / 4);
    prep_bf16_kernel<<<1024, 256>>>(W_enc, s->wenc_hi, s->wenc_lo, ATT * K2H / 4);
    prep_lo32_kernel<<<128, 256>>>(hidden, s->hlo, 2 * BATCH * HID / 4);

    // 1) dproj (split-K 8) + reduce
    gemm_tf32_kernel<64, 3, true><<<dim3(ATT / 64, 8), 256, LS_SMEM>>>(
        hidden + (size_t)BATCH * HID, s->hlo + (size_t)BATCH * HID, HID, HID,
        hidden, s->hlo, HID,
        W_dec, HID, HID, W_dec, HID,
        /*sliceCh=*/4, s->dproj_part, ATT, (size_t)BATCH * ATT, nullptr, COMP);
    dproj_reduce_kernel<<<32, 256>>>(s->dproj_part, s->dproj);

    // 2) attention energy (128x128 tiles) + fused tanh/v epilogue
    attn_mma_kernel<<<dim3(NT_ATT, M_ATT / 128), 256, ATT_SMEM>>>(
        s->enc_hi, s->enc_lo, s->wenc_hi, s->wenc_lo, s->dproj, v_w, s->part);

    // 3) embed (independent of attn result; fills x0[:, :512])
    embed_kernel<<<BATCH, 128>>>(token, emb, s->x0, s->x0lo);

    // 4) fused softmax + context, full-parallel grid (4, 64)
    softmax_context_kernel<<<dim3(4, BATCH), 256>>>(s->part, enc, out_alpha,
                                                    s->x0, s->x0lo);

    // 5) LSTM layer 0 (split-K 8)
    gemm_tf32_kernel<64, 3, true><<<dim3(4 * HID / 64, 8), 256, LS_SMEM>>>(
        s->x0, s->x0lo, X0LD, X0LD,
        hidden, s->hlo, HID,
        W_ih0, X0LD, X0LD, W_hh0, HID,
        /*sliceCh=*/14, s->gates, 4 * HID, (size_t)BATCH * 4 * HID, nullptr, COMP);
    lstm_ew_kernel<<<BATCH, 256>>>(s->gates, b_ih0, b_hh0, cell,
                                   out_hidden, out_cell, s->h0lo);

    // 6) LSTM layer 1 (split-K 8)
    gemm_tf32_kernel<64, 3, true><<<dim3(4 * HID / 64, 8), 256, LS_SMEM>>>(
        out_hidden, s->h0lo, HID, HID,
        hidden + (size_t)BATCH * HID, s->hlo + (size_t)BATCH * HID, HID,
        W_ih1, HID, HID, W_hh1, HID,
        /*sliceCh=*/8, s->gates, 4 * HID, (size_t)BATCH * 4 * HID, nullptr, COMP);
    lstm_ew_kernel<<<BATCH, 256>>>(s->gates, b_ih1, b_hh1,
                                   cell + (size_t)BATCH * HID,
                                   out_hidden + (size_t)BATCH * HID,
                                   out_cell + (size_t)BATCH * HID, s->h1lo);

    // 7) fc logits (1-term tf32, COMP2, 4-stage)
    gemm_tf32_kernel<128, 4, false><<<dim3(VOC / 128, 1), 256, FC_SMEM>>>(
        out_hidden + (size_t)BATCH * HID, nullptr, HID, HID,
        s->x0 + EMB, nullptr, X0LD,
        fc_W, 3 * HID, 3 * HID, fc_W, 3 * HID,
        /*sliceCh=*/96, out_logits, VOC, 0, fc_b, COMP2);
}

// round 16
// speedup vs baseline: 1.2066x; 1.1551x over previous
#include <cuda_runtime.h>
#include <cuda_fp16.h>
#include <cstddef>

// Problem constants
#define BATCH 64
#define SEQ   128
#define HID   1024
#define EMB   512
#define ATT   512
#define VOC   32000
#define K2H   2048
#define M_ATT (SEQ*BATCH)   // 8192
#define NT_ATT 4
#define X0LD  2560          // EMB + 2H

// Output packing: logits | new_hidden | new_cell | alpha
#define OUT_LOGITS 0
#define OUT_HIDDEN 2048000
#define OUT_CELL   (2048000 + 131072)
#define OUT_ALPHA  (2048000 + 262144)

#define COMP  1.00035f      // B-truncation only (A exact via residual)
#define COMP2 1.00070f      // A and B truncation

// -------------------- scratch --------------------
struct Scratch {
    float dproj[BATCH * ATT];
    float dproj_part[8 * BATCH * ATT];
    float part[8 * M_ATT];
    float x0[BATCH * X0LD];
    float x0lo[BATCH * X0LD];
    float gates[8 * BATCH * 4 * HID];      // 8 k-slices
    float hlo[2 * BATCH * HID];
    float h0lo[BATCH * HID];
    float h1lo[BATCH * HID];
    __half enc_h[M_ATT * K2H];             // fp16 truncation of enc
    __half wenc_h[ATT * K2H];              // fp16 hi of W_enc
    __half wenc_l[ATT * K2H];              // fp16 residual of W_enc
};
__device__ Scratch g_s;

// ===================== low-level helpers ==================================
__device__ __forceinline__ unsigned smem_u32(const void* p) {
    unsigned a;
    asm("{ .reg .u64 t; cvta.to.shared.u64 t, %1; cvt.u32.u64 %0, t; }"
        : "=r"(a) : "l"(p));
    return a;
}
__device__ __forceinline__ void ldm4(unsigned& r0, unsigned& r1,
                                     unsigned& r2, unsigned& r3, unsigned addr) {
    asm volatile("ldmatrix.sync.aligned.m8n8.x4.shared.b16 {%0,%1,%2,%3}, [%4];"
                 : "=r"(r0), "=r"(r1), "=r"(r2), "=r"(r3) : "r"(addr));
}
// fp16 mma (same fragment layout as bf16 m16n8k16)
__device__ __forceinline__ void mma_f16(float* d, const unsigned* a, const unsigned* b) {
    asm volatile(
        "mma.sync.aligned.m16n8k16.row.col.f32.f16.f16.f32 "
        "{%0,%1,%2,%3}, {%4,%5,%6,%7}, {%8,%9}, {%0,%1,%2,%3};"
        : "+f"(d[0]), "+f"(d[1]), "+f"(d[2]), "+f"(d[3])
        : "r"(a[0]), "r"(a[1]), "r"(a[2]), "r"(a[3]), "r"(b[0]), "r"(b[1]));
}
__device__ __forceinline__ void mma_tf32(float* d, const unsigned* a, const unsigned* b) {
    asm volatile(
        "mma.sync.aligned.m16n8k8.row.col.f32.tf32.tf32.f32 "
        "{%0,%1,%2,%3}, {%4,%5,%6,%7}, {%8,%9}, {%0,%1,%2,%3};"
        : "+f"(d[0]), "+f"(d[1]), "+f"(d[2]), "+f"(d[3])
        : "r"(a[0]), "r"(a[1]), "r"(a[2]), "r"(a[3]), "r"(b[0]), "r"(b[1]));
}
__device__ __forceinline__ void cpa16(unsigned dst, const void* src) {
    unsigned long long g = (unsigned long long)__cvta_generic_to_global(src);
    asm volatile("cp.async.cg.shared.global [%0], [%1], 16;"
                 :: "r"(dst), "l"(g) : "memory");
}
__device__ __forceinline__ void cpa_commit() {
    asm volatile("cp.async.commit_group;" ::: "memory");
}
template<int N> __device__ __forceinline__ void cpa_wait() {
    asm volatile("cp.async.wait_group %0;" :: "n"(N) : "memory");
}
__device__ __forceinline__ float tf32_lo(float x) {
    return x - __uint_as_float(__float_as_uint(x) & 0xffffe000u);
}
// 128-byte rows (f32 k32 tiles)
__device__ __forceinline__ unsigned swz128(int row, int colByte) {
    return row * 128 + (colByte ^ ((row & 7) << 4));
}
// 64-byte rows (f16 k32 tiles)
__device__ __forceinline__ unsigned swz64(int row, int colByte) {
    return row * 64 + (colByte ^ (((row >> 1) & 3) << 4));
}

// f16 fragment loads over 64B rows
__device__ __forceinline__ void load_afrag64(unsigned* f, unsigned base, int m0, int k0, int lane) {
    int j = lane >> 3, r = lane & 7;
    unsigned addr = base + swz64(m0 + (j & 1) * 8 + r, (k0 + (j >> 1) * 8) * 2);
    ldm4(f[0], f[1], f[2], f[3], addr);
}
__device__ __forceinline__ void load_bfrag64(unsigned* f01, unsigned* f23,
                                             unsigned base, int n0, int k0, int lane) {
    int j = lane >> 3, r = lane & 7;
    unsigned addr = base + swz64(n0 + (j >> 1) * 8 + r, (k0 + (j & 1) * 8) * 2);
    ldm4(f01[0], f01[1], f23[0], f23[1], addr);
}
// tf32 fragment loads over 128B rows
__device__ __forceinline__ void load_a32(unsigned* f, unsigned base, int m0, int k0, int lane) {
    int j = lane >> 3, r = lane & 7;
    unsigned addr = base + swz128(m0 + (j & 1) * 8 + r, k0 * 4 + (j >> 1) * 16);
    ldm4(f[0], f[1], f[2], f[3], addr);
}
__device__ __forceinline__ void load_b32(unsigned* g, unsigned base, int n0, int k0, int lane) {
    int j = lane >> 3, r = lane & 7;
    unsigned addr = base + swz128(n0 + (j >> 1) * 8 + r, k0 * 4 + (j & 1) * 16);
    ldm4(g[0], g[1], g[2], g[3], addr);
}

// ================= prepass: fp32 -> fp16 single plane =====================
__global__ void prep_f16_kernel(const float* __restrict__ src,
                                __half* __restrict__ hi, int n4)
{
    int i = blockIdx.x * blockDim.x + threadIdx.x;
    int stride = gridDim.x * blockDim.x;
    for (; i < n4; i += stride) {
        float4 v = ((const float4*)src)[i];
        __half2 h0 = __floats2half2_rn(v.x, v.y);
        __half2 h1 = __floats2half2_rn(v.z, v.w);
        ((uint2*)hi)[i] = make_uint2(*(unsigned*)&h0, *(unsigned*)&h1);
    }
}

// ================= prepass: fp32 -> fp16 hi/lo planes =====================
__global__ void prep_f16hl_kernel(const float* __restrict__ src,
                                  __half* __restrict__ hi,
                                  __half* __restrict__ lo, int n4)
{
    int i = blockIdx.x * blockDim.x + threadIdx.x;
    int stride = gridDim.x * blockDim.x;
    for (; i < n4; i += stride) {
        float4 v = ((const float4*)src)[i];
        __half2 h0 = __floats2half2_rn(v.x, v.y);
        __half2 h1 = __floats2half2_rn(v.z, v.w);
        float2 f0 = __half22float2(h0);
        float2 f1 = __half22float2(h1);
        __half2 l0 = __floats2half2_rn(v.x - f0.x, v.y - f0.y);
        __half2 l1 = __floats2half2_rn(v.z - f1.x, v.w - f1.y);
        ((uint2*)hi)[i] = make_uint2(*(unsigned*)&h0, *(unsigned*)&h1);
        ((uint2*)lo)[i] = make_uint2(*(unsigned*)&l0, *(unsigned*)&l1);
    }
}

// ================= prepass: tf32 residual plane ===========================
__global__ void prep_lo32_kernel(const float* __restrict__ src,
                                 float* __restrict__ lo, int n4)
{
    int i = blockIdx.x * blockDim.x + threadIdx.x;
    int stride = gridDim.x * blockDim.x;
    for (; i < n4; i += stride) {
        float4 v = ((const float4*)src)[i];
        float4 o;
        o.x = tf32_lo(v.x); o.y = tf32_lo(v.y);
        o.z = tf32_lo(v.z); o.w = tf32_lo(v.w);
        ((float4*)lo)[i] = o;
    }
}

// ======== attention energy: 3-stage pipelined fp16 2-term mma =============
// CTA tile 128M x 128N; K-chunk 32 fp16 (64B rows)
// stage = A 8K | Bhi 8K | Blo 8K = 24KB; 3 stages
#define ATT_STG 24576
__global__ __launch_bounds__(256, 2)
void attn_mma_kernel(const __half* __restrict__ ench,
                     const __half* __restrict__ wench,
                     const __half* __restrict__ wencl,
                     const float* __restrict__ dproj, const float* __restrict__ v_w,
                     float* __restrict__ part)
{
    extern __shared__ __align__(128) unsigned char smn[];
    const int t = threadIdx.x, lane = t & 31, wid = t >> 5;
    const int warp_m = wid & 3;
    const int warp_n = wid >> 2;
    const int nBase = blockIdx.x * 128, mBase = blockIdx.y * 128;
    const unsigned sb = smem_u32(smn);

    float acc[2][8][4];
#pragma unroll
    for (int i = 0; i < 2; i++)
#pragma unroll
        for (int j = 0; j < 8; j++)
#pragma unroll
            for (int q = 0; q < 4; q++) acc[i][j][q] = 0.f;

    const int NCH = 64;
    auto prefetch = [&](int c) {
        const int stg = c % 3;
        const int k0 = c * 32;
        const unsigned aH = sb + stg * ATT_STG;
        const unsigned bH = aH + 8192;
        const unsigned bL = aH + 16384;
#pragma unroll
        for (int j = 0; j < 2; j++) {   // A plane: 128 rows x 4 16B-units
            int u = j * 256 + t;
            int row = u >> 2, cc = u & 3;
            size_t off = (size_t)(mBase + row) * K2H + k0 + cc * 8;
            cpa16(aH + swz64(row, cc * 16), ench + off);
        }
#pragma unroll
        for (int j = 0; j < 2; j++) {   // B planes: 128 rows x 4 units
            int u = j * 256 + t;
            int row = u >> 2, cc = u & 3;
            size_t off = (size_t)(nBase + row) * K2H + k0 + cc * 8;
            unsigned dst = swz64(row, cc * 16);
            cpa16(bH + dst, wench + off);
            cpa16(bL + dst, wencl + off);
        }
        cpa_commit();
    };

    prefetch(0); prefetch(1);
    for (int c = 0; c < NCH; c++) {
        if (c + 2 < NCH) { prefetch(c + 2); cpa_wait<2>(); }
        else if (c + 1 < NCH) cpa_wait<1>();
        else cpa_wait<0>();
        __syncthreads();
        const unsigned aH = sb + (c % 3) * ATT_STG;
        const unsigned bH = aH + 8192;
        const unsigned bL = aH + 16384;
#pragma unroll
        for (int ks = 0; ks < 2; ks++) {
            const int kk = ks * 16;
            unsigned ah[2][4];
#pragma unroll
            for (int mb = 0; mb < 2; mb++)
                load_afrag64(ah[mb], aH, warp_m * 32 + mb * 16, kk, lane);
#pragma unroll
            for (int p = 0; p < 4; p++) {
                unsigned bh[2][2], bl[2][2];
                load_bfrag64(bh[0], bh[1], bH, warp_n * 64 + p * 16, kk, lane);
                load_bfrag64(bl[0], bl[1], bL, warp_n * 64 + p * 16, kk, lane);
#pragma unroll
                for (int mb = 0; mb < 2; mb++)
#pragma unroll
                    for (int q = 0; q < 2; q++) {
                        int nb = p * 2 + q;
                        mma_f16(acc[mb][nb], ah[mb], bh[q]);
                        mma_f16(acc[mb][nb], ah[mb], bl[q]);
                    }
            }
        }
        __syncthreads();
    }

    // epilogue: s[row] = sum_n tanh(acc + dproj[b][n]) * v[n]
    float* red = (float*)smn;
    const int quad = lane >> 2, qt = lane & 3;
#pragma unroll
    for (int mb = 0; mb < 2; mb++)
#pragma unroll
        for (int h = 0; h < 2; h++) {
            int row_local = warp_m * 32 + mb * 16 + quad + 8 * h;
            int g = mBase + row_local;
            int b = g & 63;
            float s = 0.f;
#pragma unroll
            for (int nb = 0; nb < 8; nb++) {
                int ng = nBase + warp_n * 64 + nb * 8 + qt * 2;
                float2 dp = *(const float2*)(dproj + (size_t)b * ATT + ng);
                float2 vv = *(const float2*)(v_w + ng);
                s += tanhf(acc[mb][nb][2 * h + 0] + dp.x) * vv.x
                   + tanhf(acc[mb][nb][2 * h + 1] + dp.y) * vv.y;
            }
            s += __shfl_xor_sync(0xffffffffu, s, 1);
            s += __shfl_xor_sync(0xffffffffu, s, 2);
            if (qt == 0) red[row_local * 2 + warp_n] = s;
        }
    __syncthreads();
    if (t < 128) {
        float s = red[t * 2] + red[t * 2 + 1];
        part[blockIdx.x * M_ATT + mBase + t] = s;
    }
}

// ========== pipelined tf32 GEMM (M=64), K-chunk 32, split-K ===============
template<int BN, int STAGES, bool ALO>
__global__ __launch_bounds__(256, (BN == 64) ? 3 : 2) void gemm_tf32_kernel(
    const float* __restrict__ A0, const float* __restrict__ A0lo, int lda0, int K0a,
    const float* __restrict__ A1, const float* __restrict__ A1lo, int lda1,
    const float* __restrict__ B0, int ldb0, int K0b,
    const float* __restrict__ B1, int ldb1,
    int sliceCh, float* __restrict__ C, int ldc, size_t cStride,
    const float* __restrict__ bias, float comp)
{
    extern __shared__ __align__(128) float smdyn[];
    constexpr int STGB = 8192 + (ALO ? 8192 : 0) + BN * 128;
    const int t = threadIdx.x, lane = t & 31, wid = t >> 5;
    const int warp_m = wid >> 2, warp_n = wid & 3;
    constexpr int NBW = BN / 32;
    const int nBase = blockIdx.x * BN;
    const int kOff = blockIdx.y * sliceCh * 32;
    C += (size_t)blockIdx.y * cStride;
    const unsigned sb = smem_u32(smdyn);

    float acc[2][NBW][4];
#pragma unroll
    for (int i = 0; i < 2; i++)
#pragma unroll
        for (int j = 0; j < NBW; j++)
#pragma unroll
            for (int q = 0; q < 4; q++) acc[i][j][q] = 0.f;

    auto prefetch = [&](int c) {
        const int k0 = kOff + c * 32;
        const unsigned aHi = sb + (c % STAGES) * STGB;
        const unsigned aLo = aHi + 8192;
        const unsigned bB  = aHi + 8192 + (ALO ? 8192 : 0);
#pragma unroll
        for (int j = 0; j < 2; j++) {
            int u = j * 256 + t;
            int row = u >> 3, cc = u & 7;
            int k = k0 + cc * 4;
            unsigned dst = swz128(row, cc * 16);
            if (k < K0a) {
                cpa16(aHi + dst, A0 + (size_t)row * lda0 + k);
                if (ALO) cpa16(aLo + dst, A0lo + (size_t)row * lda0 + k);
            } else {
                cpa16(aHi + dst, A1 + (size_t)row * lda1 + (k - K0a));
                if (ALO) cpa16(aLo + dst, A1lo + (size_t)row * lda1 + (k - K0a));
            }
        }
#pragma unroll
        for (int j = 0; j < BN / 32; j++) {
            int u = j * 256 + t;
            int row = u >> 3, cc = u & 7;
            int k = k0 + cc * 4;
            const float* src = (k < K0b)
                ? (B0 + (size_t)(nBase + row) * ldb0 + k)
                : (B1 + (size_t)(nBase + row) * ldb1 + (k - K0b));
            cpa16(bB + swz128(row, cc * 16), src);
        }
        cpa_commit();
    };

    const int nCh = sliceCh;
#pragma unroll
    for (int i = 0; i < STAGES - 1; i++)
        if (i < nCh) prefetch(i);
    for (int c = 0; c < nCh; c++) {
        if (c + STAGES - 1 < nCh) prefetch(c + STAGES - 1);
        int ahead = nCh - 1 - c;
        if (ahead > STAGES - 1) ahead = STAGES - 1;
        switch (ahead) {
            case 3: cpa_wait<3>(); break;
            case 2: cpa_wait<2>(); break;
            case 1: cpa_wait<1>(); break;
            default: cpa_wait<0>(); break;
        }
        __syncthreads();
        const unsigned aHi = sb + (c % STAGES) * STGB;
        const unsigned aLo = aHi + 8192;
        const unsigned bB  = aHi + 8192 + (ALO ? 8192 : 0);
#pragma unroll
        for (int ks = 0; ks < 4; ks++) {
            const int kk = ks * 8;
            unsigned ah[2][4], al[2][4], bg[NBW / 2][4];
#pragma unroll
            for (int mb = 0; mb < 2; mb++) {
                load_a32(ah[mb], aHi, warp_m * 32 + mb * 16, kk, lane);
                if (ALO) load_a32(al[mb], aLo, warp_m * 32 + mb * 16, kk, lane);
            }
#pragma unroll
            for (int p = 0; p < NBW / 2; p++)
                load_b32(bg[p], bB, warp_n * (8 * NBW) + p * 16, kk, lane);
#pragma unroll
            for (int mb = 0; mb < 2; mb++)
#pragma unroll
                for (int p = 0; p < NBW / 2; p++) {
                    mma_tf32(acc[mb][2 * p + 0], ah[mb], &bg[p][0]);
                    mma_tf32(acc[mb][2 * p + 1], ah[mb], &bg[p][2]);
                    if (ALO) {
                        mma_tf32(acc[mb][2 * p + 0], al[mb], &bg[p][0]);
                        mma_tf32(acc[mb][2 * p + 1], al[mb], &bg[p][2]);
                    }
                }
        }
        __syncthreads();
    }

    const int quad = lane >> 2, qt = lane & 3;
#pragma unroll
    for (int mb = 0; mb < 2; mb++)
#pragma unroll
        for (int nb = 0; nb < NBW; nb++) {
            int m = warp_m * 32 + mb * 16 + quad;
            int n = nBase + warp_n * (8 * NBW) + nb * 8 + qt * 2;
            float bx = 0.f, by = 0.f;
            if (bias) { float2 bb = *(const float2*)(bias + n); bx = bb.x; by = bb.y; }
            float2 o0, o1;
            o0.x = acc[mb][nb][0] * comp + bx; o0.y = acc[mb][nb][1] * comp + by;
            o1.x = acc[mb][nb][2] * comp + bx; o1.y = acc[mb][nb][3] * comp + by;
            *(float2*)(C + (size_t)m * ldc + n) = o0;
            *(float2*)(C + (size_t)(m + 8) * ldc + n) = o1;
        }
}

// ============ dproj partial reduce ========================================
__global__ void dproj_reduce_kernel(const float* __restrict__ part,
                                    float* __restrict__ out)
{
    int i = blockIdx.x * blockDim.x + threadIdx.x;
    float4 s = ((const float4*)part)[i];
#pragma unroll
    for (int sl = 1; sl < 8; sl++) {
        float4 v = ((const float4*)part)[sl * 8192 + i];
        s.x += v.x; s.y += v.y; s.z += v.z; s.w += v.w;
    }
    ((float4*)out)[i] = s;
}

// ===== fused softmax + context, full parallelism: grid (4, BATCH) =========
__global__ void softmax_context_kernel(const float* __restrict__ part,
                                       const float* __restrict__ enc,
                                       float* __restrict__ out_alpha,
                                       float* __restrict__ x0,
                                       float* __restrict__ x0lo)
{
    int b = blockIdx.y, t = threadIdx.x;
    __shared__ float sal[128];
    __shared__ float red[128];

    if (t < 128) {
        int r = t * 64 + b;
        float sc = 0.f;
#pragma unroll
        for (int nt = 0; nt < NT_ATT; nt++) sc += part[nt * M_ATT + r];
        sal[t] = sc;
        red[t] = sc;
    }
    __syncthreads();
    for (int off = 64; off; off >>= 1) {
        if (t < off) red[t] = fmaxf(red[t], red[t + off]);
        __syncthreads();
    }
    float mx = red[0];
    __syncthreads();
    if (t < 128) {
        float e = expf(sal[t] - mx);
        sal[t] = e;
        red[t] = e;
    }
    __syncthreads();
    for (int off = 64; off; off >>= 1) {
        if (t < off) red[t] += red[t + off];
        __syncthreads();
    }
    float inv = 1.f / red[0];
    __syncthreads();
    if (t < 128) {
        sal[t] *= inv;
        if (blockIdx.x == 0) out_alpha[b * SEQ + t] = sal[t];
    }
    __syncthreads();

    int d0 = blockIdx.x * 512 + t * 2;
    float ax = 0.f, ay = 0.f;
#pragma unroll 4
    for (int s = 0; s < SEQ; s++) {
        float2 e = *(const float2*)(enc + ((size_t)(s * 64 + b)) * K2H + d0);
        ax += sal[s] * e.x;
        ay += sal[s] * e.y;
    }
    float2 o; o.x = ax; o.y = ay;
    *(float2*)(x0 + (size_t)b * X0LD + EMB + d0) = o;
    float2 l; l.x = tf32_lo(ax); l.y = tf32_lo(ay);
    *(float2*)(x0lo + (size_t)b * X0LD + EMB + d0) = l;
}

// ================== embedding gather (+tf32 residual) =====================
__global__ void embed_kernel(const int* __restrict__ token,
                             const float* __restrict__ emb,
                             float* __restrict__ x0, float* __restrict__ x0lo)
{
    int b = blockIdx.x, t = threadIdx.x;
    float4 v = *(const float4*)(emb + (size_t)token[b] * EMB + t * 4);
    *(float4*)(x0 + (size_t)b * X0LD + t * 4) = v;
    float4 o;
    o.x = tf32_lo(v.x); o.y = tf32_lo(v.y); o.z = tf32_lo(v.z); o.w = tf32_lo(v.w);
    *(float4*)(x0lo + (size_t)b * X0LD + t * 4) = o;
}

// ========================== LSTM pointwise (sums 8 k-slices) ==============
__global__ void lstm_ew_kernel(const float* __restrict__ gates,
                               const float* __restrict__ b_ih,
                               const float* __restrict__ b_hh,
                               const float* __restrict__ c_in,
                               float* __restrict__ h_out,
                               float* __restrict__ c_out,
                               float* __restrict__ hlo_out)
{
    const size_t SL = (size_t)BATCH * 4 * HID;
    int b = blockIdx.x, t = threadIdx.x;
    const float* g0 = gates + (size_t)b * 4 * HID;
#pragma unroll
    for (int q = 0; q < 4; q++) {
        int j = t + q * 256;
        float gi = b_ih[j]            + b_hh[j];
        float gf = b_ih[HID + j]      + b_hh[HID + j];
        float gg = b_ih[2 * HID + j]  + b_hh[2 * HID + j];
        float go = b_ih[3 * HID + j]  + b_hh[3 * HID + j];
#pragma unroll
        for (int sl = 0; sl < 8; sl++) {
            const float* g = g0 + sl * SL;
            gi += g[j];
            gf += g[HID + j];
            gg += g[2 * HID + j];
            go += g[3 * HID + j];
        }
        float i_ = 1.f / (1.f + expf(-gi));
        float f_ = 1.f / (1.f + expf(-gf));
        float o_ = 1.f / (1.f + expf(-go));
        float cc = f_ * c_in[(size_t)b * HID + j] + i_ * tanhf(gg);
        float hh = o_ * tanhf(cc);
        c_out[(size_t)b * HID + j] = cc;
        h_out[(size_t)b * HID + j] = hh;
        hlo_out[(size_t)b * HID + j] = tf32_lo(hh);
    }
}

// ================================ driver ==================================
extern "C" void kernel_launch(void* const* d_in, const int* in_sizes, int n_in,
                              void* d_out, int out_size)
{
    const int*   token  = (const int*)  d_in[0];
    const float* hidden = (const float*)d_in[1];
    const float* cell   = (const float*)d_in[2];
    const float* enc    = (const float*)d_in[3];
    const float* emb    = (const float*)d_in[4];
    const float* W_enc  = (const float*)d_in[5];
    const float* W_dec  = (const float*)d_in[6];
    const float* v_w    = (const float*)d_in[7];
    const float* W_ih0  = (const float*)d_in[8];
    const float* W_hh0  = (const float*)d_in[9];
    const float* b_ih0  = (const float*)d_in[10];
    const float* b_hh0  = (const float*)d_in[11];
    const float* W_ih1  = (const float*)d_in[12];
    const float* W_hh1  = (const float*)d_in[13];
    const float* b_ih1  = (const float*)d_in[14];
    const float* b_hh1  = (const float*)d_in[15];
    const float* fc_W   = (const float*)d_in[16];
    const float* fc_b   = (const float*)d_in[17];

    float* out        = (float*)d_out;
    float* out_logits = out + OUT_LOGITS;
    float* out_hidden = out + OUT_HIDDEN;
    float* out_cell   = out + OUT_CELL;
    float* out_alpha  = out + OUT_ALPHA;

    Scratch* s = nullptr;
    cudaGetSymbolAddress((void**)&s, g_s);

    const int ATT_SMEM = 3 * ATT_STG;                       // 72 KB
    const int LS_SMEM  = 3 * (8192 + 8192 + 64 * 128);      // 72 KB
    const int FC_SMEM  = 4 * (8192 + 128 * 128);            // 96 KB
    cudaFuncSetAttribute(attn_mma_kernel,
                         cudaFuncAttributeMaxDynamicSharedMemorySize, ATT_SMEM);
    cudaFuncSetAttribute(gemm_tf32_kernel<64, 3, true>,
                         cudaFuncAttributeMaxDynamicSharedMemorySize, LS_SMEM);
    cudaFuncSetAttribute(gemm_tf32_kernel<128, 4, false>,
                         cudaFuncAttributeMaxDynamicSharedMemorySize, FC_SMEM);

    // 0) prepasses
    prep_f16_kernel<<<4096, 256>>>(enc, s->enc_h, M_ATT * K2H / 4);
    prep_f16hl_kernel<<<1024, 256>>>(W_enc, s->wenc_h, s->wenc_l, ATT * K2H / 4);
    prep_lo32_kernel<<<128, 256>>>(hidden, s->hlo, 2 * BATCH * HID / 4);

    // 1) dproj (split-K 8) + reduce
    gemm_tf32_kernel<64, 3, true><<<dim3(ATT / 64, 8), 256, LS_SMEM>>>(
        hidden + (size_t)BATCH * HID, s->hlo + (size_t)BATCH * HID, HID, HID,
        hidden, s->hlo, HID,
        W_dec, HID, HID, W_dec, HID,
        /*sliceCh=*/4, s->dproj_part, ATT, (size_t)BATCH * ATT, nullptr, COMP);
    dproj_reduce_kernel<<<32, 256>>>(s->dproj_part, s->dproj);

    // 2) attention energy (fp16 2-term, 128x128 tiles) + fused tanh/v
    attn_mma_kernel<<<dim3(NT_ATT, M_ATT / 128), 256, ATT_SMEM>>>(
        s->enc_h, s->wenc_h, s->wenc_l, s->dproj, v_w, s->part);

    // 3) embed
    embed_kernel<<<BATCH, 128>>>(token, emb, s->x0, s->x0lo);

    // 4) fused softmax + context, grid (4, 64)
    softmax_context_kernel<<<dim3(4, BATCH), 256>>>(s->part, enc, out_alpha,
                                                    s->x0, s->x0lo);

    // 5) LSTM layer 0 (split-K 8)
    gemm_tf32_kernel<64, 3, true><<<dim3(4 * HID / 64, 8), 256, LS_SMEM>>>(
        s->x0, s->x0lo, X0LD, X0LD,
        hidden, s->hlo, HID,
        W_ih0, X0LD, X0LD, W_hh0, HID,
        /*sliceCh=*/14, s->gates, 4 * HID, (size_t)BATCH * 4 * HID, nullptr, COMP);
    lstm_ew_kernel<<<BATCH, 256>>>(s->gates, b_ih0, b_hh0, cell,
                                   out_hidden, out_cell, s->h0lo);

    // 6) LSTM layer 1 (split-K 8)
    gemm_tf32_kernel<64, 3, true><<<dim3(4 * HID / 64, 8), 256, LS_SMEM>>>(
        out_hidden, s->h0lo, HID, HID,
        hidden + (size_t)BATCH * HID, s->hlo + (size_t)BATCH * HID, HID,
        W_ih1, HID, HID, W_hh1, HID,
        /*sliceCh=*/8, s->gates, 4 * HID, (size_t)BATCH * 4 * HID, nullptr, COMP);
    lstm_ew_kernel<<<BATCH, 256>>>(s->gates, b_ih1, b_hh1,
                                   cell + (size_t)BATCH * HID,
                                   out_hidden + (size_t)BATCH * HID,
                                   out_cell + (size_t)BATCH * HID, s->h1lo);

    // 7) fc logits (1-term tf32, COMP2, 4-stage)
    gemm_tf32_kernel<128, 4, false><<<dim3(VOC / 128, 1), 256, FC_SMEM>>>(
        out_hidden + (size_t)BATCH * HID, nullptr, HID, HID,
        s->x0 + EMB, nullptr, X0LD,
        fc_W, 3 * HID, 3 * HID, fc_W, 3 * HID,
        /*sliceCh=*/96, out_logits, VOC, 0, fc_b, COMP2);
}

// round 17
// speedup vs baseline: 1.3965x; 1.1574x over previous
#include <cuda_runtime.h>
#include <cuda_fp16.h>
#include <cstddef>

// Problem constants
#define BATCH 64
#define SEQ   128
#define HID   1024
#define EMB   512
#define ATT   512
#define VOC   32000
#define K2H   2048
#define M_ATT (SEQ*BATCH)   // 8192
#define NT_ATT 4
#define X0LD  2560          // EMB + 2H

// Output packing: logits | new_hidden | new_cell | alpha
#define OUT_LOGITS 0
#define OUT_HIDDEN 2048000
#define OUT_CELL   (2048000 + 131072)
#define OUT_ALPHA  (2048000 + 262144)

#define COMP  1.00035f      // B-truncation only (A exact via residual)
#define COMP2 1.00070f      // A and B truncation

// -------------------- scratch --------------------
struct Scratch {
    float dproj[BATCH * ATT];
    float dproj_part[8 * BATCH * ATT];
    float part[8 * M_ATT];
    float x0[BATCH * X0LD];
    float x0lo[BATCH * X0LD];
    float gates[8 * BATCH * 4 * HID];      // 8 k-slices
    float hlo[2 * BATCH * HID];
    float h0lo[BATCH * HID];
    float h1lo[BATCH * HID];
    __half enc_h[M_ATT * K2H];             // fp16 rounding of enc
    __half wenc_h[ATT * K2H];              // fp16 rounding of W_enc
};
__device__ Scratch g_s;

// ===================== low-level helpers ==================================
__device__ __forceinline__ unsigned smem_u32(const void* p) {
    unsigned a;
    asm("{ .reg .u64 t; cvta.to.shared.u64 t, %1; cvt.u32.u64 %0, t; }"
        : "=r"(a) : "l"(p));
    return a;
}
__device__ __forceinline__ void ldm4(unsigned& r0, unsigned& r1,
                                     unsigned& r2, unsigned& r3, unsigned addr) {
    asm volatile("ldmatrix.sync.aligned.m8n8.x4.shared.b16 {%0,%1,%2,%3}, [%4];"
                 : "=r"(r0), "=r"(r1), "=r"(r2), "=r"(r3) : "r"(addr));
}
// fp16 mma
__device__ __forceinline__ void mma_f16(float* d, const unsigned* a, const unsigned* b) {
    asm volatile(
        "mma.sync.aligned.m16n8k16.row.col.f32.f16.f16.f32 "
        "{%0,%1,%2,%3}, {%4,%5,%6,%7}, {%8,%9}, {%0,%1,%2,%3};"
        : "+f"(d[0]), "+f"(d[1]), "+f"(d[2]), "+f"(d[3])
        : "r"(a[0]), "r"(a[1]), "r"(a[2]), "r"(a[3]), "r"(b[0]), "r"(b[1]));
}
__device__ __forceinline__ void mma_tf32(float* d, const unsigned* a, const unsigned* b) {
    asm volatile(
        "mma.sync.aligned.m16n8k8.row.col.f32.tf32.tf32.f32 "
        "{%0,%1,%2,%3}, {%4,%5,%6,%7}, {%8,%9}, {%0,%1,%2,%3};"
        : "+f"(d[0]), "+f"(d[1]), "+f"(d[2]), "+f"(d[3])
        : "r"(a[0]), "r"(a[1]), "r"(a[2]), "r"(a[3]), "r"(b[0]), "r"(b[1]));
}
__device__ __forceinline__ void cpa16(unsigned dst, const void* src) {
    unsigned long long g = (unsigned long long)__cvta_generic_to_global(src);
    asm volatile("cp.async.cg.shared.global [%0], [%1], 16;"
                 :: "r"(dst), "l"(g) : "memory");
}
__device__ __forceinline__ void cpa_commit() {
    asm volatile("cp.async.commit_group;" ::: "memory");
}
template<int N> __device__ __forceinline__ void cpa_wait() {
    asm volatile("cp.async.wait_group %0;" :: "n"(N) : "memory");
}
__device__ __forceinline__ float tf32_lo(float x) {
    return x - __uint_as_float(__float_as_uint(x) & 0xffffe000u);
}
// 128-byte rows (f32 k32 tiles)
__device__ __forceinline__ unsigned swz128(int row, int colByte) {
    return row * 128 + (colByte ^ ((row & 7) << 4));
}
// 64-byte rows (f16 k32 tiles)
__device__ __forceinline__ unsigned swz64(int row, int colByte) {
    return row * 64 + (colByte ^ (((row >> 1) & 3) << 4));
}

// f16 fragment loads over 64B rows
__device__ __forceinline__ void load_afrag64(unsigned* f, unsigned base, int m0, int k0, int lane) {
    int j = lane >> 3, r = lane & 7;
    unsigned addr = base + swz64(m0 + (j & 1) * 8 + r, (k0 + (j >> 1) * 8) * 2);
    ldm4(f[0], f[1], f[2], f[3], addr);
}
__device__ __forceinline__ void load_bfrag64(unsigned* f01, unsigned* f23,
                                             unsigned base, int n0, int k0, int lane) {
    int j = lane >> 3, r = lane & 7;
    unsigned addr = base + swz64(n0 + (j >> 1) * 8 + r, (k0 + (j & 1) * 8) * 2);
    ldm4(f01[0], f01[1], f23[0], f23[1], addr);
}
// tf32 fragment loads over 128B rows
__device__ __forceinline__ void load_a32(unsigned* f, unsigned base, int m0, int k0, int lane) {
    int j = lane >> 3, r = lane & 7;
    unsigned addr = base + swz128(m0 + (j & 1) * 8 + r, k0 * 4 + (j >> 1) * 16);
    ldm4(f[0], f[1], f[2], f[3], addr);
}
__device__ __forceinline__ void load_b32(unsigned* g, unsigned base, int n0, int k0, int lane) {
    int j = lane >> 3, r = lane & 7;
    unsigned addr = base + swz128(n0 + (j >> 1) * 8 + r, k0 * 4 + (j & 1) * 16);
    ldm4(g[0], g[1], g[2], g[3], addr);
}

// ================= prepass: fp32 -> fp16 single plane =====================
__global__ void prep_f16_kernel(const float* __restrict__ src,
                                __half* __restrict__ hi, int n4)
{
    int i = blockIdx.x * blockDim.x + threadIdx.x;
    int stride = gridDim.x * blockDim.x;
    for (; i < n4; i += stride) {
        float4 v = ((const float4*)src)[i];
        __half2 h0 = __floats2half2_rn(v.x, v.y);
        __half2 h1 = __floats2half2_rn(v.z, v.w);
        ((uint2*)hi)[i] = make_uint2(*(unsigned*)&h0, *(unsigned*)&h1);
    }
}

// ================= prepass: tf32 residual plane ===========================
__global__ void prep_lo32_kernel(const float* __restrict__ src,
                                 float* __restrict__ lo, int n4)
{
    int i = blockIdx.x * blockDim.x + threadIdx.x;
    int stride = gridDim.x * blockDim.x;
    for (; i < n4; i += stride) {
        float4 v = ((const float4*)src)[i];
        float4 o;
        o.x = tf32_lo(v.x); o.y = tf32_lo(v.y);
        o.z = tf32_lo(v.z); o.w = tf32_lo(v.w);
        ((float4*)lo)[i] = o;
    }
}

// ======== attention energy: 4-stage pipelined fp16 1-term mma =============
// CTA tile 128M x 128N; K-chunk 32 fp16 (64B rows)
// stage = A 8K | B 8K = 16KB; 4 stages
#define ATT_STG 16384
__global__ __launch_bounds__(256, 2)
void attn_mma_kernel(const __half* __restrict__ ench,
                     const __half* __restrict__ wench,
                     const float* __restrict__ dproj, const float* __restrict__ v_w,
                     float* __restrict__ part)
{
    extern __shared__ __align__(128) unsigned char smn[];
    const int t = threadIdx.x, lane = t & 31, wid = t >> 5;
    const int warp_m = wid & 3;
    const int warp_n = wid >> 2;
    const int nBase = blockIdx.x * 128, mBase = blockIdx.y * 128;
    const unsigned sb = smem_u32(smn);

    float acc[2][8][4];
#pragma unroll
    for (int i = 0; i < 2; i++)
#pragma unroll
        for (int j = 0; j < 8; j++)
#pragma unroll
            for (int q = 0; q < 4; q++) acc[i][j][q] = 0.f;

    const int NCH = 64;
    auto prefetch = [&](int c) {
        const int stg = c & 3;
        const int k0 = c * 32;
        const unsigned aH = sb + stg * ATT_STG;
        const unsigned bH = aH + 8192;
#pragma unroll
        for (int j = 0; j < 2; j++) {   // A plane: 128 rows x 4 16B-units
            int u = j * 256 + t;
            int row = u >> 2, cc = u & 3;
            size_t off = (size_t)(mBase + row) * K2H + k0 + cc * 8;
            cpa16(aH + swz64(row, cc * 16), ench + off);
        }
#pragma unroll
        for (int j = 0; j < 2; j++) {   // B plane: 128 rows x 4 units
            int u = j * 256 + t;
            int row = u >> 2, cc = u & 3;
            size_t off = (size_t)(nBase + row) * K2H + k0 + cc * 8;
            cpa16(bH + swz64(row, cc * 16), wench + off);
        }
        cpa_commit();
    };

    prefetch(0); prefetch(1); prefetch(2);
    for (int c = 0; c < NCH; c++) {
        if (c + 3 < NCH) { prefetch(c + 3); cpa_wait<3>(); }
        else {
            int ahead = NCH - 1 - c;
            if (ahead >= 2) cpa_wait<2>();
            else if (ahead == 1) cpa_wait<1>();
            else cpa_wait<0>();
        }
        __syncthreads();
        const unsigned aH = sb + (c & 3) * ATT_STG;
        const unsigned bH = aH + 8192;
#pragma unroll
        for (int ks = 0; ks < 2; ks++) {
            const int kk = ks * 16;
            unsigned ah[2][4];
#pragma unroll
            for (int mb = 0; mb < 2; mb++)
                load_afrag64(ah[mb], aH, warp_m * 32 + mb * 16, kk, lane);
#pragma unroll
            for (int p = 0; p < 4; p++) {
                unsigned bh[2][2];
                load_bfrag64(bh[0], bh[1], bH, warp_n * 64 + p * 16, kk, lane);
#pragma unroll
                for (int mb = 0; mb < 2; mb++)
#pragma unroll
                    for (int q = 0; q < 2; q++)
                        mma_f16(acc[mb][p * 2 + q], ah[mb], bh[q]);
            }
        }
        __syncthreads();
    }

    // epilogue: s[row] = sum_n tanh(acc + dproj[b][n]) * v[n]
    float* red = (float*)smn;
    const int quad = lane >> 2, qt = lane & 3;
#pragma unroll
    for (int mb = 0; mb < 2; mb++)
#pragma unroll
        for (int h = 0; h < 2; h++) {
            int row_local = warp_m * 32 + mb * 16 + quad + 8 * h;
            int g = mBase + row_local;
            int b = g & 63;
            float s = 0.f;
#pragma unroll
            for (int nb = 0; nb < 8; nb++) {
                int ng = nBase + warp_n * 64 + nb * 8 + qt * 2;
                float2 dp = *(const float2*)(dproj + (size_t)b * ATT + ng);
                float2 vv = *(const float2*)(v_w + ng);
                s += tanhf(acc[mb][nb][2 * h + 0] + dp.x) * vv.x
                   + tanhf(acc[mb][nb][2 * h + 1] + dp.y) * vv.y;
            }
            s += __shfl_xor_sync(0xffffffffu, s, 1);
            s += __shfl_xor_sync(0xffffffffu, s, 2);
            if (qt == 0) red[row_local * 2 + warp_n] = s;
        }
    __syncthreads();
    if (t < 128) {
        float s = red[t * 2] + red[t * 2 + 1];
        part[blockIdx.x * M_ATT + mBase + t] = s;
    }
}

// ========== pipelined tf32 GEMM (M=64), K-chunk 32, split-K ===============
template<int BN, int STAGES, bool ALO>
__global__ __launch_bounds__(256, (BN == 64) ? 3 : 2) void gemm_tf32_kernel(
    const float* __restrict__ A0, const float* __restrict__ A0lo, int lda0, int K0a,
    const float* __restrict__ A1, const float* __restrict__ A1lo, int lda1,
    const float* __restrict__ B0, int ldb0, int K0b,
    const float* __restrict__ B1, int ldb1,
    int sliceCh, float* __restrict__ C, int ldc, size_t cStride,
    const float* __restrict__ bias, float comp)
{
    extern __shared__ __align__(128) float smdyn[];
    constexpr int STGB = 8192 + (ALO ? 8192 : 0) + BN * 128;
    const int t = threadIdx.x, lane = t & 31, wid = t >> 5;
    const int warp_m = wid >> 2, warp_n = wid & 3;
    constexpr int NBW = BN / 32;
    const int nBase = blockIdx.x * BN;
    const int kOff = blockIdx.y * sliceCh * 32;
    C += (size_t)blockIdx.y * cStride;
    const unsigned sb = smem_u32(smdyn);

    float acc[2][NBW][4];
#pragma unroll
    for (int i = 0; i < 2; i++)
#pragma unroll
        for (int j = 0; j < NBW; j++)
#pragma unroll
            for (int q = 0; q < 4; q++) acc[i][j][q] = 0.f;

    auto prefetch = [&](int c) {
        const int k0 = kOff + c * 32;
        const unsigned aHi = sb + (c % STAGES) * STGB;
        const unsigned aLo = aHi + 8192;
        const unsigned bB  = aHi + 8192 + (ALO ? 8192 : 0);
#pragma unroll
        for (int j = 0; j < 2; j++) {
            int u = j * 256 + t;
            int row = u >> 3, cc = u & 7;
            int k = k0 + cc * 4;
            unsigned dst = swz128(row, cc * 16);
            if (k < K0a) {
                cpa16(aHi + dst, A0 + (size_t)row * lda0 + k);
                if (ALO) cpa16(aLo + dst, A0lo + (size_t)row * lda0 + k);
            } else {
                cpa16(aHi + dst, A1 + (size_t)row * lda1 + (k - K0a));
                if (ALO) cpa16(aLo + dst, A1lo + (size_t)row * lda1 + (k - K0a));
            }
        }
#pragma unroll
        for (int j = 0; j < BN / 32; j++) {
            int u = j * 256 + t;
            int row = u >> 3, cc = u & 7;
            int k = k0 + cc * 4;
            const float* src = (k < K0b)
                ? (B0 + (size_t)(nBase + row) * ldb0 + k)
                : (B1 + (size_t)(nBase + row) * ldb1 + (k - K0b));
            cpa16(bB + swz128(row, cc * 16), src);
        }
        cpa_commit();
    };

    const int nCh = sliceCh;
#pragma unroll
    for (int i = 0; i < STAGES - 1; i++)
        if (i < nCh) prefetch(i);
    for (int c = 0; c < nCh; c++) {
        if (c + STAGES - 1 < nCh) prefetch(c + STAGES - 1);
        int ahead = nCh - 1 - c;
        if (ahead > STAGES - 1) ahead = STAGES - 1;
        switch (ahead) {
            case 3: cpa_wait<3>(); break;
            case 2: cpa_wait<2>(); break;
            case 1: cpa_wait<1>(); break;
            default: cpa_wait<0>(); break;
        }
        __syncthreads();
        const unsigned aHi = sb + (c % STAGES) * STGB;
        const unsigned aLo = aHi + 8192;
        const unsigned bB  = aHi + 8192 + (ALO ? 8192 : 0);
#pragma unroll
        for (int ks = 0; ks < 4; ks++) {
            const int kk = ks * 8;
            unsigned ah[2][4], al[2][4], bg[NBW / 2][4];
#pragma unroll
            for (int mb = 0; mb < 2; mb++) {
                load_a32(ah[mb], aHi, warp_m * 32 + mb * 16, kk, lane);
                if (ALO) load_a32(al[mb], aLo, warp_m * 32 + mb * 16, kk, lane);
            }
#pragma unroll
            for (int p = 0; p < NBW / 2; p++)
                load_b32(bg[p], bB, warp_n * (8 * NBW) + p * 16, kk, lane);
#pragma unroll
            for (int mb = 0; mb < 2; mb++)
#pragma unroll
                for (int p = 0; p < NBW / 2; p++) {
                    mma_tf32(acc[mb][2 * p + 0], ah[mb], &bg[p][0]);
                    mma_tf32(acc[mb][2 * p + 1], ah[mb], &bg[p][2]);
                    if (ALO) {
                        mma_tf32(acc[mb][2 * p + 0], al[mb], &bg[p][0]);
                        mma_tf32(acc[mb][2 * p + 1], al[mb], &bg[p][2]);
                    }
                }
        }
        __syncthreads();
    }

    const int quad = lane >> 2, qt = lane & 3;
#pragma unroll
    for (int mb = 0; mb < 2; mb++)
#pragma unroll
        for (int nb = 0; nb < NBW; nb++) {
            int m = warp_m * 32 + mb * 16 + quad;
            int n = nBase + warp_n * (8 * NBW) + nb * 8 + qt * 2;
            float bx = 0.f, by = 0.f;
            if (bias) { float2 bb = *(const float2*)(bias + n); bx = bb.x; by = bb.y; }
            float2 o0, o1;
            o0.x = acc[mb][nb][0] * comp + bx; o0.y = acc[mb][nb][1] * comp + by;
            o1.x = acc[mb][nb][2] * comp + bx; o1.y = acc[mb][nb][3] * comp + by;
            *(float2*)(C + (size_t)m * ldc + n) = o0;
            *(float2*)(C + (size_t)(m + 8) * ldc + n) = o1;
        }
}

// ============ dproj partial reduce ========================================
__global__ void dproj_reduce_kernel(const float* __restrict__ part,
                                    float* __restrict__ out)
{
    int i = blockIdx.x * blockDim.x + threadIdx.x;
    float4 s = ((const float4*)part)[i];
#pragma unroll
    for (int sl = 1; sl < 8; sl++) {
        float4 v = ((const float4*)part)[sl * 8192 + i];
        s.x += v.x; s.y += v.y; s.z += v.z; s.w += v.w;
    }
    ((float4*)out)[i] = s;
}

// ===== fused softmax + context, full parallelism: grid (4, BATCH) =========
__global__ void softmax_context_kernel(const float* __restrict__ part,
                                       const float* __restrict__ enc,
                                       float* __restrict__ out_alpha,
                                       float* __restrict__ x0,
                                       float* __restrict__ x0lo)
{
    int b = blockIdx.y, t = threadIdx.x;
    __shared__ float sal[128];
    __shared__ float red[128];

    if (t < 128) {
        int r = t * 64 + b;
        float sc = 0.f;
#pragma unroll
        for (int nt = 0; nt < NT_ATT; nt++) sc += part[nt * M_ATT + r];
        sal[t] = sc;
        red[t] = sc;
    }
    __syncthreads();
    for (int off = 64; off; off >>= 1) {
        if (t < off) red[t] = fmaxf(red[t], red[t + off]);
        __syncthreads();
    }
    float mx = red[0];
    __syncthreads();
    if (t < 128) {
        float e = expf(sal[t] - mx);
        sal[t] = e;
        red[t] = e;
    }
    __syncthreads();
    for (int off = 64; off; off >>= 1) {
        if (t < off) red[t] += red[t + off];
        __syncthreads();
    }
    float inv = 1.f / red[0];
    __syncthreads();
    if (t < 128) {
        sal[t] *= inv;
        if (blockIdx.x == 0) out_alpha[b * SEQ + t] = sal[t];
    }
    __syncthreads();

    int d0 = blockIdx.x * 512 + t * 2;
    float ax = 0.f, ay = 0.f;
#pragma unroll 4
    for (int s = 0; s < SEQ; s++) {
        float2 e = *(const float2*)(enc + ((size_t)(s * 64 + b)) * K2H + d0);
        ax += sal[s] * e.x;
        ay += sal[s] * e.y;
    }
    float2 o; o.x = ax; o.y = ay;
    *(float2*)(x0 + (size_t)b * X0LD + EMB + d0) = o;
    float2 l; l.x = tf32_lo(ax); l.y = tf32_lo(ay);
    *(float2*)(x0lo + (size_t)b * X0LD + EMB + d0) = l;
}

// ================== embedding gather (+tf32 residual) =====================
__global__ void embed_kernel(const int* __restrict__ token,
                             const float* __restrict__ emb,
                             float* __restrict__ x0, float* __restrict__ x0lo)
{
    int b = blockIdx.x, t = threadIdx.x;
    float4 v = *(const float4*)(emb + (size_t)token[b] * EMB + t * 4);
    *(float4*)(x0 + (size_t)b * X0LD + t * 4) = v;
    float4 o;
    o.x = tf32_lo(v.x); o.y = tf32_lo(v.y); o.z = tf32_lo(v.z); o.w = tf32_lo(v.w);
    *(float4*)(x0lo + (size_t)b * X0LD + t * 4) = o;
}

// ========================== LSTM pointwise (sums 8 k-slices) ==============
__global__ void lstm_ew_kernel(const float* __restrict__ gates,
                               const float* __restrict__ b_ih,
                               const float* __restrict__ b_hh,
                               const float* __restrict__ c_in,
                               float* __restrict__ h_out,
                               float* __restrict__ c_out,
                               float* __restrict__ hlo_out)
{
    const size_t SL = (size_t)BATCH * 4 * HID;
    int b = blockIdx.x, t = threadIdx.x;
    const float* g0 = gates + (size_t)b * 4 * HID;
#pragma unroll
    for (int q = 0; q < 4; q++) {
        int j = t + q * 256;
        float gi = b_ih[j]            + b_hh[j];
        float gf = b_ih[HID + j]      + b_hh[HID + j];
        float gg = b_ih[2 * HID + j]  + b_hh[2 * HID + j];
        float go = b_ih[3 * HID + j]  + b_hh[3 * HID + j];
#pragma unroll
        for (int sl = 0; sl < 8; sl++) {
            const float* g = g0 + sl * SL;
            gi += g[j];
            gf += g[HID + j];
            gg += g[2 * HID + j];
            go += g[3 * HID + j];
        }
        float i_ = 1.f / (1.f + expf(-gi));
        float f_ = 1.f / (1.f + expf(-gf));
        float o_ = 1.f / (1.f + expf(-go));
        float cc = f_ * c_in[(size_t)b * HID + j] + i_ * tanhf(gg);
        float hh = o_ * tanhf(cc);
        c_out[(size_t)b * HID + j] = cc;
        h_out[(size_t)b * HID + j] = hh;
        hlo_out[(size_t)b * HID + j] = tf32_lo(hh);
    }
}

// ================================ driver ==================================
extern "C" void kernel_launch(void* const* d_in, const int* in_sizes, int n_in,
                              void* d_out, int out_size)
{
    const int*   token  = (const int*)  d_in[0];
    const float* hidden = (const float*)d_in[1];
    const float* cell   = (const float*)d_in[2];
    const float* enc    = (const float*)d_in[3];
    const float* emb    = (const float*)d_in[4];
    const float* W_enc  = (const float*)d_in[5];
    const float* W_dec  = (const float*)d_in[6];
    const float* v_w    = (const float*)d_in[7];
    const float* W_ih0  = (const float*)d_in[8];
    const float* W_hh0  = (const float*)d_in[9];
    const float* b_ih0  = (const float*)d_in[10];
    const float* b_hh0  = (const float*)d_in[11];
    const float* W_ih1  = (const float*)d_in[12];
    const float* W_hh1  = (const float*)d_in[13];
    const float* b_ih1  = (const float*)d_in[14];
    const float* b_hh1  = (const float*)d_in[15];
    const float* fc_W   = (const float*)d_in[16];
    const float* fc_b   = (const float*)d_in[17];

    float* out        = (float*)d_out;
    float* out_logits = out + OUT_LOGITS;
    float* out_hidden = out + OUT_HIDDEN;
    float* out_cell   = out + OUT_CELL;
    float* out_alpha  = out + OUT_ALPHA;

    Scratch* s = nullptr;
    cudaGetSymbolAddress((void**)&s, g_s);

    const int ATT_SMEM = 4 * ATT_STG;                       // 64 KB
    const int LS_SMEM  = 3 * (8192 + 8192 + 64 * 128);      // 72 KB
    const int FC_SMEM  = 4 * (8192 + 128 * 128);            // 96 KB
    cudaFuncSetAttribute(attn_mma_kernel,
                         cudaFuncAttributeMaxDynamicSharedMemorySize, ATT_SMEM);
    cudaFuncSetAttribute(gemm_tf32_kernel<64, 3, true>,
                         cudaFuncAttributeMaxDynamicSharedMemorySize, LS_SMEM);
    cudaFuncSetAttribute(gemm_tf32_kernel<128, 4, false>,
                         cudaFuncAttributeMaxDynamicSharedMemorySize, FC_SMEM);

    // 0) prepasses
    prep_f16_kernel<<<4096, 256>>>(enc, s->enc_h, M_ATT * K2H / 4);
    prep_f16_kernel<<<1024, 256>>>(W_enc, s->wenc_h, ATT * K2H / 4);
    prep_lo32_kernel<<<128, 256>>>(hidden, s->hlo, 2 * BATCH * HID / 4);

    // 1) dproj (split-K 8) + reduce
    gemm_tf32_kernel<64, 3, true><<<dim3(ATT / 64, 8), 256, LS_SMEM>>>(
        hidden + (size_t)BATCH * HID, s->hlo + (size_t)BATCH * HID, HID, HID,
        hidden, s->hlo, HID,
        W_dec, HID, HID, W_dec, HID,
        /*sliceCh=*/4, s->dproj_part, ATT, (size_t)BATCH * ATT, nullptr, COMP);
    dproj_reduce_kernel<<<32, 256>>>(s->dproj_part, s->dproj);

    // 2) attention energy (fp16 1-term, 128x128 tiles) + fused tanh/v
    attn_mma_kernel<<<dim3(NT_ATT, M_ATT / 128), 256, ATT_SMEM>>>(
        s->enc_h, s->wenc_h, s->dproj, v_w, s->part);

    // 3) embed
    embed_kernel<<<BATCH, 128>>>(token, emb, s->x0, s->x0lo);

    // 4) fused softmax + context, grid (4, 64)
    softmax_context_kernel<<<dim3(4, BATCH), 256>>>(s->part, enc, out_alpha,
                                                    s->x0, s->x0lo);

    // 5) LSTM layer 0 (split-K 8)
    gemm_tf32_kernel<64, 3, true><<<dim3(4 * HID / 64, 8), 256, LS_SMEM>>>(
        s->x0, s->x0lo, X0LD, X0LD,
        hidden, s->hlo, HID,
        W_ih0, X0LD, X0LD, W_hh0, HID,
        /*sliceCh=*/14, s->gates, 4 * HID, (size_t)BATCH * 4 * HID, nullptr, COMP);
    lstm_ew_kernel<<<BATCH, 256>>>(s->gates, b_ih0, b_hh0, cell,
                                   out_hidden, out_cell, s->h0lo);

    // 6) LSTM layer 1 (split-K 8)
    gemm_tf32_kernel<64, 3, true><<<dim3(4 * HID / 64, 8), 256, LS_SMEM>>>(
        out_hidden, s->h0lo, HID, HID,
        hidden + (size_t)BATCH * HID, s->hlo + (size_t)BATCH * HID, HID,
        W_ih1, HID, HID, W_hh1, HID,
        /*sliceCh=*/8, s->gates, 4 * HID, (size_t)BATCH * 4 * HID, nullptr, COMP);
    lstm_ew_kernel<<<BATCH, 256>>>(s->gates, b_ih1, b_hh1,
                                   cell + (size_t)BATCH * HID,
                                   out_hidden + (size_t)BATCH * HID,
                                   out_cell + (size_t)BATCH * HID, s->h1lo);

    // 7) fc logits (1-term tf32, COMP2, 4-stage)
    gemm_tf32_kernel<128, 4, false><<<dim3(VOC / 128, 1), 256, FC_SMEM>>>(
        out_hidden + (size_t)BATCH * HID, nullptr, HID, HID,
        s->x0 + EMB, nullptr, X0LD,
        fc_W, 3 * HID, 3 * HID, fc_W, 3 * HID,
        /*sliceCh=*/96, out_logits, VOC, 0, fc_b, COMP2);
}